// round 2
// baseline (speedup 1.0000x reference)
#include <cuda_runtime.h>
#include <math.h>

#define NTOK 2304
#define CDIM 256
#define BATCH 4
#define NHEAD 8
#define HD 32
#define MDIM 128
#define MHD 16
#define HID 1024
#define HH 48
#define WW 48
#define SCALE 0.17677669529663687f

// ---------------- scratch (static __device__, no allocs) ----------------
__device__ float g_S [BATCH*NTOK*CDIM];     // normed tokens (feat_s)
__device__ float g_Q [BATCH*NTOK*CDIM];
__device__ float g_KV[BATCH*NTOK*2*CDIM];
__device__ float g_XO[BATCH*NTOK*CDIM];     // attn @ v (head-merged)
__device__ float g_CR[BATCH*NTOK*MDIM];     // attn @ ceh
__device__ float g_S2[BATCH*NTOK*CDIM];     // after proj + residual
__device__ float g_N2[BATCH*NTOK*CDIM];     // norm2 output
__device__ float g_Y1[BATCH*NTOK*HID];      // fc1 out
__device__ float g_Y2[BATCH*NTOK*HID];      // after dwconv+gelu
__device__ float g_Z [BATCH*NTOK*CDIM];     // fc2 out + residual
__device__ float g_MO[BATCH*NTOK*MDIM];     // motion (token-major)

// ---------------- tiled transpose: in (B,R,C) -> out (B,C,R) ----------------
__global__ void transpose_kernel(const float* __restrict__ in, float* __restrict__ out,
                                 int R, int C) {
    __shared__ float t[32][33];
    int b = blockIdx.z;
    int r0 = blockIdx.y * 32, c0 = blockIdx.x * 32;
    const float* ib = in + (size_t)b * R * C;
    float* ob = out + (size_t)b * R * C;
    #pragma unroll
    for (int i = threadIdx.y; i < 32; i += 8) {
        t[i][threadIdx.x] = ib[(size_t)(r0 + i) * C + c0 + threadIdx.x];
    }
    __syncthreads();
    #pragma unroll
    for (int i = threadIdx.y; i < 32; i += 8) {
        ob[(size_t)(c0 + i) * R + r0 + threadIdx.x] = t[threadIdx.x][i];
    }
}

// ---------------- LayerNorm over last dim (C=256), warp per row ----------------
__global__ void ln_rows_kernel(const float* __restrict__ in, float* __restrict__ out,
                               const float* __restrict__ g, const float* __restrict__ bb,
                               int rows) {
    int warp = (blockIdx.x * blockDim.x + threadIdx.x) >> 5;
    int lane = threadIdx.x & 31;
    if (warp >= rows) return;
    const float* row = in + (size_t)warp * CDIM;
    float* orow = out + (size_t)warp * CDIM;
    float v[8];
    float s = 0.f, s2 = 0.f;
    #pragma unroll
    for (int i = 0; i < 8; i++) {
        v[i] = row[lane + i * 32];
        s += v[i];
        s2 += v[i] * v[i];
    }
    #pragma unroll
    for (int o = 16; o; o >>= 1) {
        s  += __shfl_xor_sync(0xffffffffu, s,  o);
        s2 += __shfl_xor_sync(0xffffffffu, s2, o);
    }
    float mean = s * (1.f / CDIM);
    float var  = s2 * (1.f / CDIM) - mean * mean;
    float rstd = rsqrtf(var + 1e-5f);
    #pragma unroll
    for (int i = 0; i < 8; i++) {
        int c = lane + i * 32;
        orow[c] = (v[i] - mean) * rstd * g[c] + bb[c];
    }
}

// ---------------- generic tiled SGEMM ----------------
// C[M,N] = op(A)[M,K] @ B[K,N] + bias[N] (+ resid[M,N])
// swapHalf: logical row (b,n) reads physical row (b^2, n)  [feat_t]
// subCE:    A element = A[m][k] - ce(n,k) (motion input)
__global__ __launch_bounds__(256)
void gemm_kernel(const float* __restrict__ A, const float* __restrict__ B,
                 const float* __restrict__ bias, const float* __restrict__ resid,
                 float* __restrict__ C, int M, int K, int N,
                 int swapHalf, int subCE,
                 const float* __restrict__ corw, const float* __restrict__ corb) {
    __shared__ float As[16][68];
    __shared__ float Bs[16][68];
    int tid = threadIdx.x;
    int tx = tid & 15, ty = tid >> 4;
    int m0 = blockIdx.y * 64, n0 = blockIdx.x * 64;
    float acc[4][4] = {};

    int arow = tid >> 2, aq = tid & 3;      // A loader: row 0..63, 4-float quad
    int gm = m0 + arow;
    int gmp = gm;
    if (swapHalf) { int b = gm / NTOK; int n = gm - b * NTOK; gmp = (b ^ 2) * NTOK + n; }
    float cx = 0.f, cy = 0.f;
    if (subCE) {
        int n = gm % NTOK;
        cx = -1.f + 2.f * (float)(n % WW) * (1.f / 47.f);
        cy = -1.f + 2.f * (float)(n / WW) * (1.f / 47.f);
    }
    int bk = tid >> 4, bq = tid & 15;       // B loader

    for (int k0 = 0; k0 < K; k0 += 16) {
        // load A tile (transposed into smem)
        if (subCE) {
            #pragma unroll
            for (int i = 0; i < 4; i++) {
                int k = k0 + aq * 4 + i;
                float ce = cx * corw[k] + cy * corw[128 + k] + corb[k];
                As[aq * 4 + i][arow] = A[(size_t)gmp * K + k] - ce;
            }
        } else {
            float4 a4 = *(const float4*)&A[(size_t)gmp * K + k0 + aq * 4];
            As[aq * 4 + 0][arow] = a4.x;
            As[aq * 4 + 1][arow] = a4.y;
            As[aq * 4 + 2][arow] = a4.z;
            As[aq * 4 + 3][arow] = a4.w;
        }
        // load B tile
        float4 b4 = *(const float4*)&B[(size_t)(k0 + bk) * N + n0 + bq * 4];
        *(float4*)&Bs[bk][bq * 4] = b4;
        __syncthreads();
        #pragma unroll
        for (int k = 0; k < 16; k++) {
            float4 af = *(float4*)&As[k][ty * 4];
            float4 bf = *(float4*)&Bs[k][tx * 4];
            acc[0][0] += af.x * bf.x; acc[0][1] += af.x * bf.y; acc[0][2] += af.x * bf.z; acc[0][3] += af.x * bf.w;
            acc[1][0] += af.y * bf.x; acc[1][1] += af.y * bf.y; acc[1][2] += af.y * bf.z; acc[1][3] += af.y * bf.w;
            acc[2][0] += af.z * bf.x; acc[2][1] += af.z * bf.y; acc[2][2] += af.z * bf.z; acc[2][3] += af.z * bf.w;
            acc[3][0] += af.w * bf.x; acc[3][1] += af.w * bf.y; acc[3][2] += af.w * bf.z; acc[3][3] += af.w * bf.w;
        }
        __syncthreads();
    }
    float4 bi = *(const float4*)&bias[n0 + tx * 4];
    #pragma unroll
    for (int i = 0; i < 4; i++) {
        int m = m0 + ty * 4 + i;
        float4 r = make_float4(acc[i][0] + bi.x, acc[i][1] + bi.y,
                               acc[i][2] + bi.z, acc[i][3] + bi.w);
        if (resid) {
            float4 rv = *(const float4*)&resid[(size_t)m * N + n0 + tx * 4];
            r.x += rv.x; r.y += rv.y; r.z += rv.z; r.w += rv.w;
        }
        *(float4*)&C[(size_t)m * N + n0 + tx * 4] = r;
    }
}

// ---------------- fused flash attention + motion aggregation ----------------
// per (b, h): out_v = softmax(QK^T*scale) @ V, out_ce = same attn @ CE_h
// CE computed inline from the coordinate grid. W smem tile padded to 64 cols
// (48 live) so the PV stage uses pure float4 fragments.
__global__ __launch_bounds__(256)
void flash_kernel(const float* __restrict__ qb, const float* __restrict__ kvb,
                  const float* __restrict__ corw, const float* __restrict__ corb,
                  float* __restrict__ xo, float* __restrict__ cro) {
    extern __shared__ float sm[];
    float (*Qs)[64] = (float(*)[64])(sm);            // 32x64
    float (*Ks)[64] = (float(*)[64])(sm + 2048);     // 32x64
    float (*Ps)[68] = (float(*)[68])(sm + 4096);     // 64x68
    float (*Pt)[68] = (float(*)[68])(sm + 8448);     // 64x68
    float (*Wt)[64] = (float(*)[64])(sm + 12800);    // 64x64 ([V|CE|0])
    float* alpha_s = sm + 16896;                     // 64
    float* l_s     = sm + 16960;                     // 64

    int tid = threadIdx.x;
    int tx = tid & 15, ty = tid >> 4;
    int m0 = blockIdx.x * 64;
    int h  = blockIdx.y;
    int b  = blockIdx.z;

    const float* qbase = qb + ((size_t)b * NTOK) * CDIM + h * HD;
    const float* kbase = kvb + ((size_t)b * NTOK) * (2 * CDIM) + h * HD;
    const float* vbase = kbase + CDIM;
    const float* cwh = corw + h * MHD;
    const float* cbh = corb + h * MHD;

    // load Q transposed
    #pragma unroll
    for (int it = 0; it < 2; it++) {
        int idx = tid + it * 256;
        int row = idx >> 3, q = idx & 7;
        float4 v = *(const float4*)&qbase[(size_t)(m0 + row) * CDIM + q * 4];
        Qs[q * 4 + 0][row] = v.x;
        Qs[q * 4 + 1][row] = v.y;
        Qs[q * 4 + 2][row] = v.z;
        Qs[q * 4 + 3][row] = v.w;
    }

    float m_i = -1e30f, l_i = 0.f;
    float O[4][4] = {};

    for (int kt = 0; kt < NTOK / 64; kt++) {
        int n0 = kt * 64;
        __syncthreads();  // prior-iter consumers of Ks/Wt/Pt are done
        // K tile (transposed)
        #pragma unroll
        for (int it = 0; it < 2; it++) {
            int idx = tid + it * 256;
            int row = idx >> 3, q = idx & 7;
            float4 v = *(const float4*)&kbase[(size_t)(n0 + row) * (2 * CDIM) + q * 4];
            Ks[q * 4 + 0][row] = v.x;
            Ks[q * 4 + 1][row] = v.y;
            Ks[q * 4 + 2][row] = v.z;
            Ks[q * 4 + 3][row] = v.w;
        }
        // V tile (direct)
        #pragma unroll
        for (int it = 0; it < 2; it++) {
            int idx = tid + it * 256;
            int row = idx >> 3, q = idx & 7;
            float4 v = *(const float4*)&vbase[(size_t)(n0 + row) * (2 * CDIM) + q * 4];
            *(float4*)&Wt[row][q * 4] = v;
        }
        // CE tile cols 32..47, zeros 48..63
        #pragma unroll
        for (int it = 0; it < 8; it++) {
            int idx = tid + it * 256;
            int row = idx >> 5, c = idx & 31;
            float val = 0.f;
            if (c < 16) {
                int kn = n0 + row;
                float xf = -1.f + 2.f * (float)(kn % WW) * (1.f / 47.f);
                float yf = -1.f + 2.f * (float)(kn / WW) * (1.f / 47.f);
                val = xf * cwh[c] + yf * cwh[128 + c] + cbh[c];
            }
            Wt[row][32 + c] = val;
        }
        __syncthreads();
        // scores
        float s[4][4] = {};
        #pragma unroll
        for (int k = 0; k < 32; k++) {
            float4 qf = *(float4*)&Qs[k][ty * 4];
            float4 kf = *(float4*)&Ks[k][tx * 4];
            s[0][0] += qf.x * kf.x; s[0][1] += qf.x * kf.y; s[0][2] += qf.x * kf.z; s[0][3] += qf.x * kf.w;
            s[1][0] += qf.y * kf.x; s[1][1] += qf.y * kf.y; s[1][2] += qf.y * kf.z; s[1][3] += qf.y * kf.w;
            s[2][0] += qf.z * kf.x; s[2][1] += qf.z * kf.y; s[2][2] += qf.z * kf.z; s[2][3] += qf.z * kf.w;
            s[3][0] += qf.w * kf.x; s[3][1] += qf.w * kf.y; s[3][2] += qf.w * kf.z; s[3][3] += qf.w * kf.w;
        }
        #pragma unroll
        for (int i = 0; i < 4; i++) {
            float4 wv = make_float4(s[i][0] * SCALE, s[i][1] * SCALE,
                                    s[i][2] * SCALE, s[i][3] * SCALE);
            *(float4*)&Ps[ty * 4 + i][tx * 4] = wv;
        }
        __syncthreads();
        // online softmax, write P transposed
        if (tid < 64) {
            int r = tid;
            float mx = -1e30f;
            #pragma unroll 8
            for (int c = 0; c < 64; c++) mx = fmaxf(mx, Ps[r][c]);
            float nm = fmaxf(m_i, mx);
            float al = __expf(m_i - nm);
            float sum = 0.f;
            #pragma unroll 8
            for (int c = 0; c < 64; c++) {
                float p = __expf(Ps[r][c] - nm);
                Pt[c][r] = p;
                sum += p;
            }
            l_i = l_i * al + sum;
            m_i = nm;
            alpha_s[r] = al;
        }
        __syncthreads();
        // rescale + P @ [V|CE]
        float a0 = alpha_s[ty * 4 + 0];
        float a1 = alpha_s[ty * 4 + 1];
        float a2 = alpha_s[ty * 4 + 2];
        float a3 = alpha_s[ty * 4 + 3];
        #pragma unroll
        for (int j = 0; j < 4; j++) {
            O[0][j] *= a0; O[1][j] *= a1; O[2][j] *= a2; O[3][j] *= a3;
        }
        #pragma unroll 16
        for (int kk = 0; kk < 64; kk++) {
            float4 pf = *(float4*)&Pt[kk][ty * 4];
            float4 wf = *(float4*)&Wt[kk][tx * 4];
            O[0][0] += pf.x * wf.x; O[0][1] += pf.x * wf.y; O[0][2] += pf.x * wf.z; O[0][3] += pf.x * wf.w;
            O[1][0] += pf.y * wf.x; O[1][1] += pf.y * wf.y; O[1][2] += pf.y * wf.z; O[1][3] += pf.y * wf.w;
            O[2][0] += pf.z * wf.x; O[2][1] += pf.z * wf.y; O[2][2] += pf.z * wf.z; O[2][3] += pf.z * wf.w;
            O[3][0] += pf.w * wf.x; O[3][1] += pf.w * wf.y; O[3][2] += pf.w * wf.z; O[3][3] += pf.w * wf.w;
        }
    }
    __syncthreads();
    if (tid < 64) l_s[tid] = l_i;
    __syncthreads();
    int c0 = tx * 4;
    #pragma unroll
    for (int i = 0; i < 4; i++) {
        int r = ty * 4 + i;
        float inv = 1.f / l_s[r];
        size_t gm = (size_t)b * NTOK + m0 + r;
        if (c0 < 32) {
            float4 ov = make_float4(O[i][0] * inv, O[i][1] * inv, O[i][2] * inv, O[i][3] * inv);
            *(float4*)&xo[gm * CDIM + h * HD + c0] = ov;
        } else if (c0 < 48) {
            float4 ov = make_float4(O[i][0] * inv, O[i][1] * inv, O[i][2] * inv, O[i][3] * inv);
            *(float4*)&cro[gm * MDIM + h * MHD + (c0 - 32)] = ov;
        }
    }
}

// ---------------- depthwise 3x3 conv + bias + exact GELU ----------------
// input/out token-major (B,N,HID); coalesced over channels
__global__ void dwconv_gelu_kernel(const float* __restrict__ y, const float* __restrict__ w,
                                   const float* __restrict__ bias, float* __restrict__ out) {
    int n = blockIdx.x;
    int b = blockIdx.y;
    int h = n / WW, wc = n % WW;
    const float* yb = y + (size_t)b * NTOK * HID;
    #pragma unroll
    for (int rep = 0; rep < HID / 256; rep++) {
        int ch = threadIdx.x + rep * 256;
        float acc = bias[ch];
        #pragma unroll
        for (int dh = -1; dh <= 1; dh++) {
            int hh2 = h + dh;
            if (hh2 < 0 || hh2 >= HH) continue;
            #pragma unroll
            for (int dw = -1; dw <= 1; dw++) {
                int wc2 = wc + dw;
                if (wc2 < 0 || wc2 >= WW) continue;
                acc += yb[(size_t)(hh2 * WW + wc2) * HID + ch] * w[ch * 9 + (dh + 1) * 3 + (dw + 1)];
            }
        }
        float gv = 0.5f * acc * (1.f + erff(acc * 0.70710678118654752f));
        out[((size_t)b * NTOK + n) * HID + ch] = gv;
    }
}

// ---------------- launch ----------------
extern "C" void kernel_launch(void* const* d_in, const int* in_sizes, int n_in,
                              void* d_out, int out_size) {
    const float* feat0   = (const float*)d_in[0];
    const float* feat1   = (const float*)d_in[1];
    const float* norm1_g = (const float*)d_in[2];
    const float* norm1_b = (const float*)d_in[3];
    const float* norm2_g = (const float*)d_in[4];
    const float* norm2_b = (const float*)d_in[5];
    const float* q_w     = (const float*)d_in[6];
    const float* q_b     = (const float*)d_in[7];
    const float* kv_w    = (const float*)d_in[8];
    const float* kv_b    = (const float*)d_in[9];
    const float* cor_w   = (const float*)d_in[10];
    const float* cor_b   = (const float*)d_in[11];
    const float* mot_w   = (const float*)d_in[12];
    const float* mot_b   = (const float*)d_in[13];
    const float* proj_w  = (const float*)d_in[14];
    const float* proj_b  = (const float*)d_in[15];
    const float* fc1_w   = (const float*)d_in[16];
    const float* fc1_b   = (const float*)d_in[17];
    const float* dw_w    = (const float*)d_in[18];
    const float* dw_b    = (const float*)d_in[19];
    const float* fc2_w   = (const float*)d_in[20];
    const float* fc2_b   = (const float*)d_in[21];

    float* out_main   = (float*)d_out;                          // (4,256,2304)
    float* out_motion = out_main + (size_t)BATCH * CDIM * NTOK; // (4,128,2304)

    float *pS, *pQ, *pKV, *pXO, *pCR, *pS2, *pN2, *pY1, *pY2, *pZ, *pMO;
    cudaGetSymbolAddress((void**)&pS,  g_S);
    cudaGetSymbolAddress((void**)&pQ,  g_Q);
    cudaGetSymbolAddress((void**)&pKV, g_KV);
    cudaGetSymbolAddress((void**)&pXO, g_XO);
    cudaGetSymbolAddress((void**)&pCR, g_CR);
    cudaGetSymbolAddress((void**)&pS2, g_S2);
    cudaGetSymbolAddress((void**)&pN2, g_N2);
    cudaGetSymbolAddress((void**)&pY1, g_Y1);
    cudaGetSymbolAddress((void**)&pY2, g_Y2);
    cudaGetSymbolAddress((void**)&pZ,  g_Z);
    cudaGetSymbolAddress((void**)&pMO, g_MO);

    dim3 tb(32, 8);

    // tokens: transpose (b,C,N)->(b,N,C) into S, then LN1 in place over all 4 batches
    transpose_kernel<<<dim3(NTOK / 32, CDIM / 32, 2), tb>>>(feat0, pS, CDIM, NTOK);
    transpose_kernel<<<dim3(NTOK / 32, CDIM / 32, 2), tb>>>(feat1, pS + 2 * (size_t)NTOK * CDIM, CDIM, NTOK);
    ln_rows_kernel<<<(BATCH * NTOK) / 8, 256>>>(pS, pS, norm1_g, norm1_b, BATCH * NTOK);

    int M = BATCH * NTOK;
    // q = S @ q_w + q_b
    gemm_kernel<<<dim3(CDIM / 64, M / 64), 256>>>(pS, q_w, q_b, nullptr, pQ,
                                                  M, CDIM, CDIM, 0, 0, nullptr, nullptr);
    // kv = feat_t @ kv_w + kv_b  (batch-swapped rows of S)
    gemm_kernel<<<dim3(2 * CDIM / 64, M / 64), 256>>>(pS, kv_w, kv_b, nullptr, pKV,
                                                      M, CDIM, 2 * CDIM, 1, 0, nullptr, nullptr);
    // fused attention + motion aggregation
    size_t fsmem = 17024 * sizeof(float);
    cudaFuncSetAttribute(flash_kernel, cudaFuncAttributeMaxDynamicSharedMemorySize, (int)fsmem);
    flash_kernel<<<dim3(NTOK / 64, NHEAD, BATCH), 256, fsmem>>>(pQ, pKV, cor_w, cor_b, pXO, pCR);
    // proj + residual
    gemm_kernel<<<dim3(CDIM / 64, M / 64), 256>>>(pXO, proj_w, proj_b, pS, pS2,
                                                  M, CDIM, CDIM, 0, 0, nullptr, nullptr);
    // norm2
    ln_rows_kernel<<<(BATCH * NTOK) / 8, 256>>>(pS2, pN2, norm2_g, norm2_b, BATCH * NTOK);
    // fc1
    gemm_kernel<<<dim3(HID / 64, M / 64), 256>>>(pN2, fc1_w, fc1_b, nullptr, pY1,
                                                 M, CDIM, HID, 0, 0, nullptr, nullptr);
    // depthwise conv + gelu
    dwconv_gelu_kernel<<<dim3(NTOK, BATCH), 256>>>(pY1, dw_w, dw_b, pY2);
    // fc2 + residual
    gemm_kernel<<<dim3(CDIM / 64, M / 64), 256>>>(pY2, fc2_w, fc2_b, pS2, pZ,
                                                  M, HID, CDIM, 0, 0, nullptr, nullptr);
    // motion: (crev - ce) @ mot_w + mot_b
    gemm_kernel<<<dim3(MDIM / 64, M / 64), 256>>>(pCR, mot_w, mot_b, nullptr, pMO,
                                                  M, MDIM, MDIM, 0, 1, cor_w, cor_b);
    // final transposes into d_out
    transpose_kernel<<<dim3(CDIM / 32, NTOK / 32, BATCH), tb>>>(pZ, out_main, NTOK, CDIM);
    transpose_kernel<<<dim3(MDIM / 32, NTOK / 32, BATCH), tb>>>(pMO, out_motion, NTOK, MDIM);
}

// round 3
// speedup vs baseline: 1.1346x; 1.1346x over previous
#include <cuda_runtime.h>
#include <math.h>

#define NTOK 2304
#define CDIM 256
#define BATCH 4
#define NHEAD 8
#define HD 32
#define MDIM 128
#define MHD 16
#define HID 1024
#define HH 48
#define WW 48
#define SCALE 0.17677669529663687f

// ---------------- scratch (static __device__, no allocs) ----------------
__device__ float g_S [BATCH*NTOK*CDIM];     // normed tokens (feat_s)
__device__ float g_Q [BATCH*NTOK*CDIM];
__device__ float g_KV[BATCH*NTOK*2*CDIM];
__device__ float g_XO[BATCH*NTOK*CDIM];     // attn @ v (head-merged)
__device__ float g_CR[BATCH*NTOK*MDIM];     // attn @ ceh
__device__ float g_S2[BATCH*NTOK*CDIM];     // after proj + residual
__device__ float g_N2[BATCH*NTOK*CDIM];     // norm2 output
__device__ float g_Y1[BATCH*NTOK*HID];      // fc1 out
__device__ float g_Y2[BATCH*NTOK*HID];      // after dwconv+gelu
__device__ float g_Z [BATCH*NTOK*CDIM];     // fc2 out + residual
__device__ float g_MO[BATCH*NTOK*MDIM];     // motion (token-major)

// ---------------- tiled transpose: in (B,R,C) -> out (B,C,R) ----------------
__global__ void transpose_kernel(const float* __restrict__ in, float* __restrict__ out,
                                 int R, int C) {
    __shared__ float t[32][33];
    int b = blockIdx.z;
    int r0 = blockIdx.y * 32, c0 = blockIdx.x * 32;
    const float* ib = in + (size_t)b * R * C;
    float* ob = out + (size_t)b * R * C;
    #pragma unroll
    for (int i = threadIdx.y; i < 32; i += 8) {
        t[i][threadIdx.x] = ib[(size_t)(r0 + i) * C + c0 + threadIdx.x];
    }
    __syncthreads();
    #pragma unroll
    for (int i = threadIdx.y; i < 32; i += 8) {
        ob[(size_t)(c0 + i) * R + r0 + threadIdx.x] = t[threadIdx.x][i];
    }
}

// ---------------- LayerNorm over last dim (C=256), warp per row ----------------
__global__ void ln_rows_kernel(const float* __restrict__ in, float* __restrict__ out,
                               const float* __restrict__ g, const float* __restrict__ bb,
                               int rows) {
    int warp = (blockIdx.x * blockDim.x + threadIdx.x) >> 5;
    int lane = threadIdx.x & 31;
    if (warp >= rows) return;
    const float* row = in + (size_t)warp * CDIM;
    float* orow = out + (size_t)warp * CDIM;
    float v[8];
    float s = 0.f, s2 = 0.f;
    #pragma unroll
    for (int i = 0; i < 8; i++) {
        v[i] = row[lane + i * 32];
        s += v[i];
        s2 += v[i] * v[i];
    }
    #pragma unroll
    for (int o = 16; o; o >>= 1) {
        s  += __shfl_xor_sync(0xffffffffu, s,  o);
        s2 += __shfl_xor_sync(0xffffffffu, s2, o);
    }
    float mean = s * (1.f / CDIM);
    float var  = s2 * (1.f / CDIM) - mean * mean;
    float rstd = rsqrtf(var + 1e-5f);
    #pragma unroll
    for (int i = 0; i < 8; i++) {
        int c = lane + i * 32;
        orow[c] = (v[i] - mean) * rstd * g[c] + bb[c];
    }
}

// ---------------- tiled SGEMM: 128x128 block, 8x8 microtile ----------------
// C[M,N] = op(A)[M,K] @ B[K,N] + bias[N] (+ resid[M,N])
// swapHalf: logical row (b,n) reads physical row (b^2, n)  [feat_t]
// subCE:    A element = A[m][k] - ce(n,k) (motion input)
__global__ __launch_bounds__(256)
void gemm_kernel(const float* __restrict__ A, const float* __restrict__ B,
                 const float* __restrict__ bias, const float* __restrict__ resid,
                 float* __restrict__ C, int M, int K, int N,
                 int swapHalf, int subCE,
                 const float* __restrict__ corw, const float* __restrict__ corb) {
    __shared__ float As[16][132];
    __shared__ float Bs[16][132];
    int tid = threadIdx.x;
    int tx = tid & 15, ty = tid >> 4;
    int m0 = blockIdx.y * 128, n0 = blockIdx.x * 128;
    float acc[8][8] = {};

    // A-loader setup: two chunks, each thread covers (arow, 4-float quad aq)
    int gmp_l[2]; float cx_l[2], cy_l[2]; int arow_l[2], aq_l[2];
    #pragma unroll
    for (int it = 0; it < 2; it++) {
        int idx = tid + it * 256;
        int arow = idx >> 2, aq = idx & 3;
        arow_l[it] = arow; aq_l[it] = aq;
        int gm = m0 + arow;
        int gmp = gm;
        if (swapHalf) { int b = gm / NTOK; int n = gm - b * NTOK; gmp = (b ^ 2) * NTOK + n; }
        gmp_l[it] = gmp;
        cx_l[it] = 0.f; cy_l[it] = 0.f;
        if (subCE) {
            int n = gm % NTOK;
            cx_l[it] = -1.f + 2.f * (float)(n % WW) * (1.f / 47.f);
            cy_l[it] = -1.f + 2.f * (float)(n / WW) * (1.f / 47.f);
        }
    }

    for (int k0 = 0; k0 < K; k0 += 16) {
        // A tile (transposed into smem)
        #pragma unroll
        for (int it = 0; it < 2; it++) {
            int arow = arow_l[it], aq = aq_l[it], gmp = gmp_l[it];
            if (subCE) {
                #pragma unroll
                for (int i = 0; i < 4; i++) {
                    int k = k0 + aq * 4 + i;
                    float ce = cx_l[it] * corw[k] + cy_l[it] * corw[128 + k] + corb[k];
                    As[aq * 4 + i][arow] = A[(size_t)gmp * K + k] - ce;
                }
            } else {
                float4 a4 = *(const float4*)&A[(size_t)gmp * K + k0 + aq * 4];
                As[aq * 4 + 0][arow] = a4.x;
                As[aq * 4 + 1][arow] = a4.y;
                As[aq * 4 + 2][arow] = a4.z;
                As[aq * 4 + 3][arow] = a4.w;
            }
        }
        // B tile
        #pragma unroll
        for (int it = 0; it < 2; it++) {
            int idx = tid + it * 256;
            int brow = idx >> 5, bc = idx & 31;
            *(float4*)&Bs[brow][bc * 4] = *(const float4*)&B[(size_t)(k0 + brow) * N + n0 + bc * 4];
        }
        __syncthreads();
        #pragma unroll
        for (int k = 0; k < 16; k++) {
            float av[8], bv[8];
            *(float4*)&av[0] = *(float4*)&As[k][ty * 8];
            *(float4*)&av[4] = *(float4*)&As[k][ty * 8 + 4];
            *(float4*)&bv[0] = *(float4*)&Bs[k][tx * 8];
            *(float4*)&bv[4] = *(float4*)&Bs[k][tx * 8 + 4];
            #pragma unroll
            for (int i = 0; i < 8; i++)
                #pragma unroll
                for (int j = 0; j < 8; j++)
                    acc[i][j] += av[i] * bv[j];
        }
        __syncthreads();
    }
    float bi[8];
    *(float4*)&bi[0] = *(const float4*)&bias[n0 + tx * 8];
    *(float4*)&bi[4] = *(const float4*)&bias[n0 + tx * 8 + 4];
    #pragma unroll
    for (int i = 0; i < 8; i++) {
        int m = m0 + ty * 8 + i;
        float r[8];
        #pragma unroll
        for (int j = 0; j < 8; j++) r[j] = acc[i][j] + bi[j];
        if (resid) {
            float rv[8];
            *(float4*)&rv[0] = *(const float4*)&resid[(size_t)m * N + n0 + tx * 8];
            *(float4*)&rv[4] = *(const float4*)&resid[(size_t)m * N + n0 + tx * 8 + 4];
            #pragma unroll
            for (int j = 0; j < 8; j++) r[j] += rv[j];
        }
        *(float4*)&C[(size_t)m * N + n0 + tx * 8]     = *(float4*)&r[0];
        *(float4*)&C[(size_t)m * N + n0 + tx * 8 + 4] = *(float4*)&r[4];
    }
}

// ---------------- fused flash attention + motion aggregation ----------------
// per (b, h): out_v = softmax(QK^T*scale) @ V, out_ce = same attn @ CE_h
// Register-resident online softmax: row max/sum reduced via shfl across the
// 16 tx lanes; P written transposed with STS.128; no serial softmax phase.
__global__ __launch_bounds__(256)
void flash_kernel(const float* __restrict__ qb, const float* __restrict__ kvb,
                  const float* __restrict__ corw, const float* __restrict__ corb,
                  float* __restrict__ xo, float* __restrict__ cro) {
    extern __shared__ float sm[];
    float (*Qs)[64] = (float(*)[64])(sm);            // 32x64
    float (*Ks)[64] = (float(*)[64])(sm + 2048);     // 32x64
    float (*Pt)[68] = (float(*)[68])(sm + 4096);     // 64x68 (P transposed)
    float (*Wt)[64] = (float(*)[64])(sm + 8448);     // 64x64 ([V|CE|0])

    int tid = threadIdx.x;
    int tx = tid & 15, ty = tid >> 4;
    int m0 = blockIdx.x * 64;
    int h  = blockIdx.y;
    int b  = blockIdx.z;

    const float* qbase = qb + ((size_t)b * NTOK) * CDIM + h * HD;
    const float* kbase = kvb + ((size_t)b * NTOK) * (2 * CDIM) + h * HD;
    const float* vbase = kbase + CDIM;
    const float* cwh = corw + h * MHD;
    const float* cbh = corb + h * MHD;

    // load Q transposed
    #pragma unroll
    for (int it = 0; it < 2; it++) {
        int idx = tid + it * 256;
        int row = idx >> 3, q = idx & 7;
        float4 v = *(const float4*)&qbase[(size_t)(m0 + row) * CDIM + q * 4];
        Qs[q * 4 + 0][row] = v.x;
        Qs[q * 4 + 1][row] = v.y;
        Qs[q * 4 + 2][row] = v.z;
        Qs[q * 4 + 3][row] = v.w;
    }

    float m_r[4] = {-1e30f, -1e30f, -1e30f, -1e30f};
    float l_r[4] = {};
    float O[4][4] = {};

    for (int kt = 0; kt < NTOK / 64; kt++) {
        int n0 = kt * 64;
        __syncthreads();  // prior-iter consumers of Ks/Wt/Pt are done
        // K tile (transposed)
        #pragma unroll
        for (int it = 0; it < 2; it++) {
            int idx = tid + it * 256;
            int row = idx >> 3, q = idx & 7;
            float4 v = *(const float4*)&kbase[(size_t)(n0 + row) * (2 * CDIM) + q * 4];
            Ks[q * 4 + 0][row] = v.x;
            Ks[q * 4 + 1][row] = v.y;
            Ks[q * 4 + 2][row] = v.z;
            Ks[q * 4 + 3][row] = v.w;
        }
        // V tile (direct)
        #pragma unroll
        for (int it = 0; it < 2; it++) {
            int idx = tid + it * 256;
            int row = idx >> 3, q = idx & 7;
            float4 v = *(const float4*)&vbase[(size_t)(n0 + row) * (2 * CDIM) + q * 4];
            *(float4*)&Wt[row][q * 4] = v;
        }
        // CE tile cols 32..47, zeros 48..63
        #pragma unroll
        for (int it = 0; it < 8; it++) {
            int idx = tid + it * 256;
            int row = idx >> 5, c = idx & 31;
            float val = 0.f;
            if (c < 16) {
                int kn = n0 + row;
                float xf = -1.f + 2.f * (float)(kn % WW) * (1.f / 47.f);
                float yf = -1.f + 2.f * (float)(kn / WW) * (1.f / 47.f);
                val = xf * cwh[c] + yf * cwh[128 + c] + cbh[c];
            }
            Wt[row][32 + c] = val;
        }
        __syncthreads();
        // scores (4x4 register block)
        float s[4][4] = {};
        #pragma unroll
        for (int k = 0; k < 32; k++) {
            float4 qf = *(float4*)&Qs[k][ty * 4];
            float4 kf = *(float4*)&Ks[k][tx * 4];
            s[0][0] += qf.x * kf.x; s[0][1] += qf.x * kf.y; s[0][2] += qf.x * kf.z; s[0][3] += qf.x * kf.w;
            s[1][0] += qf.y * kf.x; s[1][1] += qf.y * kf.y; s[1][2] += qf.y * kf.z; s[1][3] += qf.y * kf.w;
            s[2][0] += qf.z * kf.x; s[2][1] += qf.z * kf.y; s[2][2] += qf.z * kf.z; s[2][3] += qf.z * kf.w;
            s[3][0] += qf.w * kf.x; s[3][1] += qf.w * kf.y; s[3][2] += qf.w * kf.z; s[3][3] += qf.w * kf.w;
        }
        // register online softmax: reduce over 16 tx lanes via shfl
        float alpha[4];
        #pragma unroll
        for (int i = 0; i < 4; i++) {
            float mx = fmaxf(fmaxf(s[i][0], s[i][1]), fmaxf(s[i][2], s[i][3]));
            #pragma unroll
            for (int o = 1; o < 16; o <<= 1)
                mx = fmaxf(mx, __shfl_xor_sync(0xffffffffu, mx, o));
            mx *= SCALE;
            float nm = fmaxf(m_r[i], mx);
            alpha[i] = __expf(m_r[i] - nm);
            m_r[i] = nm;
            float sum = 0.f;
            #pragma unroll
            for (int j = 0; j < 4; j++) {
                float p = __expf(s[i][j] * SCALE - nm);
                s[i][j] = p;
                sum += p;
            }
            #pragma unroll
            for (int o = 1; o < 16; o <<= 1)
                sum += __shfl_xor_sync(0xffffffffu, sum, o);
            l_r[i] = l_r[i] * alpha[i] + sum;
            #pragma unroll
            for (int j = 0; j < 4; j++) O[i][j] *= alpha[i];
        }
        // write P transposed: thread owns rows ty*4..+3 of cols tx*4..+3
        #pragma unroll
        for (int j = 0; j < 4; j++) {
            *(float4*)&Pt[tx * 4 + j][ty * 4] =
                make_float4(s[0][j], s[1][j], s[2][j], s[3][j]);
        }
        __syncthreads();
        // P @ [V|CE]
        #pragma unroll 16
        for (int kk = 0; kk < 64; kk++) {
            float4 pf = *(float4*)&Pt[kk][ty * 4];
            float4 wf = *(float4*)&Wt[kk][tx * 4];
            O[0][0] += pf.x * wf.x; O[0][1] += pf.x * wf.y; O[0][2] += pf.x * wf.z; O[0][3] += pf.x * wf.w;
            O[1][0] += pf.y * wf.x; O[1][1] += pf.y * wf.y; O[1][2] += pf.y * wf.z; O[1][3] += pf.y * wf.w;
            O[2][0] += pf.z * wf.x; O[2][1] += pf.z * wf.y; O[2][2] += pf.z * wf.z; O[2][3] += pf.z * wf.w;
            O[3][0] += pf.w * wf.x; O[3][1] += pf.w * wf.y; O[3][2] += pf.w * wf.z; O[3][3] += pf.w * wf.w;
        }
    }
    int c0 = tx * 4;
    #pragma unroll
    for (int i = 0; i < 4; i++) {
        int r = ty * 4 + i;
        float inv = 1.f / l_r[i];
        size_t gm = (size_t)b * NTOK + m0 + r;
        if (c0 < 32) {
            float4 ov = make_float4(O[i][0] * inv, O[i][1] * inv, O[i][2] * inv, O[i][3] * inv);
            *(float4*)&xo[gm * CDIM + h * HD + c0] = ov;
        } else if (c0 < 48) {
            float4 ov = make_float4(O[i][0] * inv, O[i][1] * inv, O[i][2] * inv, O[i][3] * inv);
            *(float4*)&cro[gm * MDIM + h * MHD + (c0 - 32)] = ov;
        }
    }
}

// ---------------- depthwise 3x3 conv + bias + exact GELU ----------------
// input/out token-major (B,N,HID); coalesced over channels
__global__ void dwconv_gelu_kernel(const float* __restrict__ y, const float* __restrict__ w,
                                   const float* __restrict__ bias, float* __restrict__ out) {
    int n = blockIdx.x;
    int b = blockIdx.y;
    int h = n / WW, wc = n % WW;
    const float* yb = y + (size_t)b * NTOK * HID;
    #pragma unroll
    for (int rep = 0; rep < HID / 256; rep++) {
        int ch = threadIdx.x + rep * 256;
        float acc = bias[ch];
        #pragma unroll
        for (int dh = -1; dh <= 1; dh++) {
            int hh2 = h + dh;
            if (hh2 < 0 || hh2 >= HH) continue;
            #pragma unroll
            for (int dw = -1; dw <= 1; dw++) {
                int wc2 = wc + dw;
                if (wc2 < 0 || wc2 >= WW) continue;
                acc += yb[(size_t)(hh2 * WW + wc2) * HID + ch] * w[ch * 9 + (dh + 1) * 3 + (dw + 1)];
            }
        }
        float gv = 0.5f * acc * (1.f + erff(acc * 0.70710678118654752f));
        out[((size_t)b * NTOK + n) * HID + ch] = gv;
    }
}

// ---------------- launch ----------------
extern "C" void kernel_launch(void* const* d_in, const int* in_sizes, int n_in,
                              void* d_out, int out_size) {
    const float* feat0   = (const float*)d_in[0];
    const float* feat1   = (const float*)d_in[1];
    const float* norm1_g = (const float*)d_in[2];
    const float* norm1_b = (const float*)d_in[3];
    const float* norm2_g = (const float*)d_in[4];
    const float* norm2_b = (const float*)d_in[5];
    const float* q_w     = (const float*)d_in[6];
    const float* q_b     = (const float*)d_in[7];
    const float* kv_w    = (const float*)d_in[8];
    const float* kv_b    = (const float*)d_in[9];
    const float* cor_w   = (const float*)d_in[10];
    const float* cor_b   = (const float*)d_in[11];
    const float* mot_w   = (const float*)d_in[12];
    const float* mot_b   = (const float*)d_in[13];
    const float* proj_w  = (const float*)d_in[14];
    const float* proj_b  = (const float*)d_in[15];
    const float* fc1_w   = (const float*)d_in[16];
    const float* fc1_b   = (const float*)d_in[17];
    const float* dw_w    = (const float*)d_in[18];
    const float* dw_b    = (const float*)d_in[19];
    const float* fc2_w   = (const float*)d_in[20];
    const float* fc2_b   = (const float*)d_in[21];

    float* out_main   = (float*)d_out;                          // (4,256,2304)
    float* out_motion = out_main + (size_t)BATCH * CDIM * NTOK; // (4,128,2304)

    float *pS, *pQ, *pKV, *pXO, *pCR, *pS2, *pN2, *pY1, *pY2, *pZ, *pMO;
    cudaGetSymbolAddress((void**)&pS,  g_S);
    cudaGetSymbolAddress((void**)&pQ,  g_Q);
    cudaGetSymbolAddress((void**)&pKV, g_KV);
    cudaGetSymbolAddress((void**)&pXO, g_XO);
    cudaGetSymbolAddress((void**)&pCR, g_CR);
    cudaGetSymbolAddress((void**)&pS2, g_S2);
    cudaGetSymbolAddress((void**)&pN2, g_N2);
    cudaGetSymbolAddress((void**)&pY1, g_Y1);
    cudaGetSymbolAddress((void**)&pY2, g_Y2);
    cudaGetSymbolAddress((void**)&pZ,  g_Z);
    cudaGetSymbolAddress((void**)&pMO, g_MO);

    dim3 tb(32, 8);

    // tokens: transpose (b,C,N)->(b,N,C) into S, then LN1 in place over all 4 batches
    transpose_kernel<<<dim3(NTOK / 32, CDIM / 32, 2), tb>>>(feat0, pS, CDIM, NTOK);
    transpose_kernel<<<dim3(NTOK / 32, CDIM / 32, 2), tb>>>(feat1, pS + 2 * (size_t)NTOK * CDIM, CDIM, NTOK);
    ln_rows_kernel<<<(BATCH * NTOK) / 8, 256>>>(pS, pS, norm1_g, norm1_b, BATCH * NTOK);

    int M = BATCH * NTOK;
    // q = S @ q_w + q_b
    gemm_kernel<<<dim3(CDIM / 128, M / 128), 256>>>(pS, q_w, q_b, nullptr, pQ,
                                                    M, CDIM, CDIM, 0, 0, nullptr, nullptr);
    // kv = feat_t @ kv_w + kv_b  (batch-swapped rows of S)
    gemm_kernel<<<dim3(2 * CDIM / 128, M / 128), 256>>>(pS, kv_w, kv_b, nullptr, pKV,
                                                        M, CDIM, 2 * CDIM, 1, 0, nullptr, nullptr);
    // fused attention + motion aggregation
    size_t fsmem = 12544 * sizeof(float);
    cudaFuncSetAttribute(flash_kernel, cudaFuncAttributeMaxDynamicSharedMemorySize, (int)fsmem);
    flash_kernel<<<dim3(NTOK / 64, NHEAD, BATCH), 256, fsmem>>>(pQ, pKV, cor_w, cor_b, pXO, pCR);
    // proj + residual
    gemm_kernel<<<dim3(CDIM / 128, M / 128), 256>>>(pXO, proj_w, proj_b, pS, pS2,
                                                    M, CDIM, CDIM, 0, 0, nullptr, nullptr);
    // norm2
    ln_rows_kernel<<<(BATCH * NTOK) / 8, 256>>>(pS2, pN2, norm2_g, norm2_b, BATCH * NTOK);
    // fc1
    gemm_kernel<<<dim3(HID / 128, M / 128), 256>>>(pN2, fc1_w, fc1_b, nullptr, pY1,
                                                   M, CDIM, HID, 0, 0, nullptr, nullptr);
    // depthwise conv + gelu
    dwconv_gelu_kernel<<<dim3(NTOK, BATCH), 256>>>(pY1, dw_w, dw_b, pY2);
    // fc2 + residual
    gemm_kernel<<<dim3(CDIM / 128, M / 128), 256>>>(pY2, fc2_w, fc2_b, pS2, pZ,
                                                    M, HID, CDIM, 0, 0, nullptr, nullptr);
    // motion: (crev - ce) @ mot_w + mot_b
    gemm_kernel<<<dim3(MDIM / 128, M / 128), 256>>>(pCR, mot_w, mot_b, nullptr, pMO,
                                                    M, MDIM, MDIM, 0, 1, cor_w, cor_b);
    // final transposes into d_out
    transpose_kernel<<<dim3(CDIM / 32, NTOK / 32, BATCH), tb>>>(pZ, out_main, NTOK, CDIM);
    transpose_kernel<<<dim3(MDIM / 32, NTOK / 32, BATCH), tb>>>(pMO, out_motion, NTOK, MDIM);
}

// round 4
// speedup vs baseline: 2.1890x; 1.9293x over previous
#include <cuda_runtime.h>
#include <math.h>

#define NTOK 2304
#define CDIM 256
#define BATCH 4
#define NHEAD 8
#define HD 32
#define MDIM 128
#define MHD 16
#define HID 1024
#define HH 48
#define WW 48
#define SCALE 0.17677669529663687f

// ---------------- scratch (static __device__, no allocs) ----------------
__device__ float g_S [BATCH*NTOK*CDIM];     // normed tokens (feat_s)
__device__ float g_Q [BATCH*NTOK*CDIM];
__device__ float g_KV[BATCH*NTOK*2*CDIM];
__device__ float g_XO[BATCH*NTOK*CDIM];     // attn @ v (head-merged)
__device__ float g_CR[BATCH*NTOK*MDIM];     // attn @ ceh
__device__ float g_S2[BATCH*NTOK*CDIM];     // after proj + residual
__device__ float g_N2[BATCH*NTOK*CDIM];     // norm2 output
__device__ float g_Y1[BATCH*NTOK*HID];      // fc1 out
__device__ float g_Y2[BATCH*NTOK*HID];      // after dwconv+gelu
__device__ float g_Z [BATCH*NTOK*CDIM];     // fc2 out + residual
__device__ float g_MO[BATCH*NTOK*MDIM];     // motion (token-major)

// ---------------- tf32 helpers ----------------
__device__ __forceinline__ unsigned f2tf32(float f) {
    unsigned r;
    asm("cvt.rna.tf32.f32 %0, %1;" : "=r"(r) : "f"(f));
    return r;
}
__device__ __forceinline__ void mma_tf32(float* c,
    unsigned a0, unsigned a1, unsigned a2, unsigned a3,
    unsigned b0, unsigned b1) {
    asm("mma.sync.aligned.m16n8k8.row.col.f32.tf32.tf32.f32 "
        "{%0,%1,%2,%3}, {%4,%5,%6,%7}, {%8,%9}, {%0,%1,%2,%3};"
        : "+f"(c[0]), "+f"(c[1]), "+f"(c[2]), "+f"(c[3])
        : "r"(a0), "r"(a1), "r"(a2), "r"(a3), "r"(b0), "r"(b1));
}

// ---------------- tiled transpose: in (B,R,C) -> out (B,C,R) ----------------
__global__ void transpose_kernel(const float* __restrict__ in, float* __restrict__ out,
                                 int R, int C) {
    __shared__ float t[32][33];
    int b = blockIdx.z;
    int r0 = blockIdx.y * 32, c0 = blockIdx.x * 32;
    const float* ib = in + (size_t)b * R * C;
    float* ob = out + (size_t)b * R * C;
    #pragma unroll
    for (int i = threadIdx.y; i < 32; i += 8) {
        t[i][threadIdx.x] = ib[(size_t)(r0 + i) * C + c0 + threadIdx.x];
    }
    __syncthreads();
    #pragma unroll
    for (int i = threadIdx.y; i < 32; i += 8) {
        ob[(size_t)(c0 + i) * R + r0 + threadIdx.x] = t[threadIdx.x][i];
    }
}

// ---------------- LayerNorm over last dim (C=256), warp per row ----------------
__global__ void ln_rows_kernel(const float* __restrict__ in, float* __restrict__ out,
                               const float* __restrict__ g, const float* __restrict__ bb,
                               int rows) {
    int warp = (blockIdx.x * blockDim.x + threadIdx.x) >> 5;
    int lane = threadIdx.x & 31;
    if (warp >= rows) return;
    const float* row = in + (size_t)warp * CDIM;
    float* orow = out + (size_t)warp * CDIM;
    float v[8];
    float s = 0.f, s2 = 0.f;
    #pragma unroll
    for (int i = 0; i < 8; i++) {
        v[i] = row[lane + i * 32];
        s += v[i];
        s2 += v[i] * v[i];
    }
    #pragma unroll
    for (int o = 16; o; o >>= 1) {
        s  += __shfl_xor_sync(0xffffffffu, s,  o);
        s2 += __shfl_xor_sync(0xffffffffu, s2, o);
    }
    float mean = s * (1.f / CDIM);
    float var  = s2 * (1.f / CDIM) - mean * mean;
    float rstd = rsqrtf(var + 1e-5f);
    #pragma unroll
    for (int i = 0; i < 8; i++) {
        int c = lane + i * 32;
        orow[c] = (v[i] - mean) * rstd * g[c] + bb[c];
    }
}

// ---------------- tiled SGEMM: 128x128 block, 8x8 microtile ----------------
__global__ __launch_bounds__(256)
void gemm_kernel(const float* __restrict__ A, const float* __restrict__ B,
                 const float* __restrict__ bias, const float* __restrict__ resid,
                 float* __restrict__ C, int M, int K, int N,
                 int swapHalf, int subCE,
                 const float* __restrict__ corw, const float* __restrict__ corb) {
    __shared__ float As[16][132];
    __shared__ float Bs[16][132];
    int tid = threadIdx.x;
    int tx = tid & 15, ty = tid >> 4;
    int m0 = blockIdx.y * 128, n0 = blockIdx.x * 128;
    float acc[8][8] = {};

    int gmp_l[2]; float cx_l[2], cy_l[2]; int arow_l[2], aq_l[2];
    #pragma unroll
    for (int it = 0; it < 2; it++) {
        int idx = tid + it * 256;
        int arow = idx >> 2, aq = idx & 3;
        arow_l[it] = arow; aq_l[it] = aq;
        int gm = m0 + arow;
        int gmp = gm;
        if (swapHalf) { int b = gm / NTOK; int n = gm - b * NTOK; gmp = (b ^ 2) * NTOK + n; }
        gmp_l[it] = gmp;
        cx_l[it] = 0.f; cy_l[it] = 0.f;
        if (subCE) {
            int n = gm % NTOK;
            cx_l[it] = -1.f + 2.f * (float)(n % WW) * (1.f / 47.f);
            cy_l[it] = -1.f + 2.f * (float)(n / WW) * (1.f / 47.f);
        }
    }

    for (int k0 = 0; k0 < K; k0 += 16) {
        #pragma unroll
        for (int it = 0; it < 2; it++) {
            int arow = arow_l[it], aq = aq_l[it], gmp = gmp_l[it];
            if (subCE) {
                #pragma unroll
                for (int i = 0; i < 4; i++) {
                    int k = k0 + aq * 4 + i;
                    float ce = cx_l[it] * corw[k] + cy_l[it] * corw[128 + k] + corb[k];
                    As[aq * 4 + i][arow] = A[(size_t)gmp * K + k] - ce;
                }
            } else {
                float4 a4 = *(const float4*)&A[(size_t)gmp * K + k0 + aq * 4];
                As[aq * 4 + 0][arow] = a4.x;
                As[aq * 4 + 1][arow] = a4.y;
                As[aq * 4 + 2][arow] = a4.z;
                As[aq * 4 + 3][arow] = a4.w;
            }
        }
        #pragma unroll
        for (int it = 0; it < 2; it++) {
            int idx = tid + it * 256;
            int brow = idx >> 5, bc = idx & 31;
            *(float4*)&Bs[brow][bc * 4] = *(const float4*)&B[(size_t)(k0 + brow) * N + n0 + bc * 4];
        }
        __syncthreads();
        #pragma unroll
        for (int k = 0; k < 16; k++) {
            float av[8], bv[8];
            *(float4*)&av[0] = *(float4*)&As[k][ty * 8];
            *(float4*)&av[4] = *(float4*)&As[k][ty * 8 + 4];
            *(float4*)&bv[0] = *(float4*)&Bs[k][tx * 8];
            *(float4*)&bv[4] = *(float4*)&Bs[k][tx * 8 + 4];
            #pragma unroll
            for (int i = 0; i < 8; i++)
                #pragma unroll
                for (int j = 0; j < 8; j++)
                    acc[i][j] += av[i] * bv[j];
        }
        __syncthreads();
    }
    float bi[8];
    *(float4*)&bi[0] = *(const float4*)&bias[n0 + tx * 8];
    *(float4*)&bi[4] = *(const float4*)&bias[n0 + tx * 8 + 4];
    #pragma unroll
    for (int i = 0; i < 8; i++) {
        int m = m0 + ty * 8 + i;
        float r[8];
        #pragma unroll
        for (int j = 0; j < 8; j++) r[j] = acc[i][j] + bi[j];
        if (resid) {
            float rv[8];
            *(float4*)&rv[0] = *(const float4*)&resid[(size_t)m * N + n0 + tx * 8];
            *(float4*)&rv[4] = *(const float4*)&resid[(size_t)m * N + n0 + tx * 8 + 4];
            #pragma unroll
            for (int j = 0; j < 8; j++) r[j] += rv[j];
        }
        *(float4*)&C[(size_t)m * N + n0 + tx * 8]     = *(float4*)&r[0];
        *(float4*)&C[(size_t)m * N + n0 + tx * 8 + 4] = *(float4*)&r[4];
    }
}

// ---------------- fused flash attention + motion aggregation (tf32 mma) ----------
// BM=128 q rows per CTA (8 warps x 16 rows), BN=64 keys per tile.
// QK^T and P@[V|CE] run on tensor cores (m16n8k8 tf32). Per-warp row ownership:
// softmax reduces within a thread-quad only; P round-trips smem per-warp (no sync).
__global__ __launch_bounds__(256)
void flash_kernel(const float* __restrict__ qb, const float* __restrict__ kvb,
                  const float* __restrict__ corw, const float* __restrict__ corb,
                  float* __restrict__ xo, float* __restrict__ cro) {
    extern __shared__ float sm[];
    float (*Ks)[36] = (float(*)[36])(sm);                 // 64 keys x 32 dims (tf32 bits)
    float (*Wt)[56] = (float(*)[56])(sm + 2304);          // 64 keys x [V(32)|CE(16)] (tf32 bits)
    float (*Pi)[76] = (float(*)[76])(sm + 2304 + 3584);   // 128 rows x 64 probs (tf32 bits)

    int tid = threadIdx.x;
    int wid = tid >> 5, lane = tid & 31;
    int gid = lane >> 2, tig = lane & 3;
    int m0 = blockIdx.x * 128;
    int h  = blockIdx.y;
    int b  = blockIdx.z;

    const float* qbase = qb + ((size_t)b * NTOK) * CDIM + h * HD;
    const float* kbase = kvb + ((size_t)b * NTOK) * (2 * CDIM) + h * HD;
    const float* vbase = kbase + CDIM;
    const float* cwh = corw + h * MHD;
    const float* cbh = corb + h * MHD;

    // Q fragments: rows (wid*16+gid, +8), k 0..31 -> 4 k-steps, resident in regs
    unsigned qa[4][4];
    {
        size_t r0 = (size_t)(m0 + wid * 16 + gid) * CDIM;
        size_t r1 = r0 + 8 * CDIM;
        #pragma unroll
        for (int ks = 0; ks < 4; ks++) {
            qa[ks][0] = f2tf32(qbase[r0 + ks * 8 + tig]);
            qa[ks][1] = f2tf32(qbase[r1 + ks * 8 + tig]);
            qa[ks][2] = f2tf32(qbase[r0 + ks * 8 + tig + 4]);
            qa[ks][3] = f2tf32(qbase[r1 + ks * 8 + tig + 4]);
        }
    }

    float m_r[2] = {-1e30f, -1e30f};
    float l_r[2] = {0.f, 0.f};
    float O[6][4] = {};   // 6 n-tiles (48 cols: V 0..31, CE 32..47)

    int lkey = tid >> 2;            // loader: 4 threads per key
    int ld0  = (tid & 3) * 8;       // 8 dims each
    int lc0  = (tid & 3) * 4;       // CE: 4 cols each

    for (int kt = 0; kt < NTOK / 64; kt++) {
        int n0g = kt * 64;
        __syncthreads();   // protect Ks/Wt overwrite vs prior-iter readers
        // K tile -> Ks[key][dim] (tf32 bits)
        {
            const float* kr = &kbase[(size_t)(n0g + lkey) * (2 * CDIM) + ld0];
            float4 v0 = *(const float4*)kr;
            float4 v1 = *(const float4*)(kr + 4);
            uint4 u0 = make_uint4(f2tf32(v0.x), f2tf32(v0.y), f2tf32(v0.z), f2tf32(v0.w));
            uint4 u1 = make_uint4(f2tf32(v1.x), f2tf32(v1.y), f2tf32(v1.z), f2tf32(v1.w));
            *(uint4*)&Ks[lkey][ld0]     = u0;
            *(uint4*)&Ks[lkey][ld0 + 4] = u1;
            // V tile -> Wt[key][0..31]
            const float* vr = &vbase[(size_t)(n0g + lkey) * (2 * CDIM) + ld0];
            float4 w0 = *(const float4*)vr;
            float4 w1 = *(const float4*)(vr + 4);
            uint4 x0 = make_uint4(f2tf32(w0.x), f2tf32(w0.y), f2tf32(w0.z), f2tf32(w0.w));
            uint4 x1 = make_uint4(f2tf32(w1.x), f2tf32(w1.y), f2tf32(w1.z), f2tf32(w1.w));
            *(uint4*)&Wt[lkey][ld0]     = x0;
            *(uint4*)&Wt[lkey][ld0 + 4] = x1;
            // CE tile -> Wt[key][32..47]
            int kn = n0g + lkey;
            float xf = -1.f + 2.f * (float)(kn % WW) * (1.f / 47.f);
            float yf = -1.f + 2.f * (float)(kn / WW) * (1.f / 47.f);
            uint4 ce;
            ce.x = f2tf32(xf * cwh[lc0 + 0] + yf * cwh[128 + lc0 + 0] + cbh[lc0 + 0]);
            ce.y = f2tf32(xf * cwh[lc0 + 1] + yf * cwh[128 + lc0 + 1] + cbh[lc0 + 1]);
            ce.z = f2tf32(xf * cwh[lc0 + 2] + yf * cwh[128 + lc0 + 2] + cbh[lc0 + 2]);
            ce.w = f2tf32(xf * cwh[lc0 + 3] + yf * cwh[128 + lc0 + 3] + cbh[lc0 + 3]);
            *(uint4*)&Wt[lkey][32 + lc0] = ce;
        }
        __syncthreads();

        // QK^T: 8 n-tiles x 4 k-steps
        float c[8][4] = {};
        #pragma unroll
        for (int j = 0; j < 8; j++) {
            #pragma unroll
            for (int ks = 0; ks < 4; ks++) {
                unsigned b0 = __float_as_uint(Ks[j * 8 + gid][ks * 8 + tig]);
                unsigned b1 = __float_as_uint(Ks[j * 8 + gid][ks * 8 + tig + 4]);
                mma_tf32(c[j], qa[ks][0], qa[ks][1], qa[ks][2], qa[ks][3], b0, b1);
            }
        }

        // online softmax per row-pair (rows gid and gid+8 within warp's 16)
        #pragma unroll
        for (int r = 0; r < 2; r++) {
            float mx = -1e30f;
            #pragma unroll
            for (int j = 0; j < 8; j++)
                mx = fmaxf(mx, fmaxf(c[j][r * 2], c[j][r * 2 + 1]));
            mx = fmaxf(mx, __shfl_xor_sync(0xffffffffu, mx, 1));
            mx = fmaxf(mx, __shfl_xor_sync(0xffffffffu, mx, 2));
            mx *= SCALE;
            float nm = fmaxf(m_r[r], mx);
            float alpha = __expf(m_r[r] - nm);
            m_r[r] = nm;
            int prow = wid * 16 + gid + 8 * r;
            float sum = 0.f;
            #pragma unroll
            for (int j = 0; j < 8; j++) {
                float p0 = __expf(c[j][r * 2]     * SCALE - nm);
                float p1 = __expf(c[j][r * 2 + 1] * SCALE - nm);
                sum += p0 + p1;
                uint2 pp = make_uint2(f2tf32(p0), f2tf32(p1));
                *(uint2*)&Pi[prow][j * 8 + 2 * tig] = pp;
            }
            sum += __shfl_xor_sync(0xffffffffu, sum, 1);
            sum += __shfl_xor_sync(0xffffffffu, sum, 2);
            l_r[r] = l_r[r] * alpha + sum;
            #pragma unroll
            for (int j = 0; j < 6; j++) {
                O[j][r * 2]     *= alpha;
                O[j][r * 2 + 1] *= alpha;
            }
        }
        // PV: each warp reads only its own Pi rows (written by itself) -> no sync
        #pragma unroll
        for (int ks = 0; ks < 8; ks++) {
            int kk = ks * 8;
            unsigned a0 = __float_as_uint(Pi[wid * 16 + gid][kk + tig]);
            unsigned a1 = __float_as_uint(Pi[wid * 16 + gid + 8][kk + tig]);
            unsigned a2 = __float_as_uint(Pi[wid * 16 + gid][kk + tig + 4]);
            unsigned a3 = __float_as_uint(Pi[wid * 16 + gid + 8][kk + tig + 4]);
            #pragma unroll
            for (int j = 0; j < 6; j++) {
                unsigned b0 = __float_as_uint(Wt[kk + tig][j * 8 + gid]);
                unsigned b1 = __float_as_uint(Wt[kk + tig + 4][j * 8 + gid]);
                mma_tf32(O[j], a0, a1, a2, a3, b0, b1);
            }
        }
    }

    // epilogue: normalize and write xo (cols 0..31) / cro (cols 32..47)
    #pragma unroll
    for (int r = 0; r < 2; r++) {
        float inv = 1.f / l_r[r];
        size_t gm = (size_t)b * NTOK + m0 + wid * 16 + gid + 8 * r;
        #pragma unroll
        for (int j = 0; j < 4; j++) {
            float2 ov = make_float2(O[j][r * 2] * inv, O[j][r * 2 + 1] * inv);
            *(float2*)&xo[gm * CDIM + h * HD + j * 8 + 2 * tig] = ov;
        }
        #pragma unroll
        for (int j = 4; j < 6; j++) {
            float2 ov = make_float2(O[j][r * 2] * inv, O[j][r * 2 + 1] * inv);
            *(float2*)&cro[gm * MDIM + h * MHD + (j - 4) * 8 + 2 * tig] = ov;
        }
    }
}

// ---------------- depthwise 3x3 conv + bias + exact GELU ----------------
__global__ void dwconv_gelu_kernel(const float* __restrict__ y, const float* __restrict__ w,
                                   const float* __restrict__ bias, float* __restrict__ out) {
    int n = blockIdx.x;
    int b = blockIdx.y;
    int h = n / WW, wc = n % WW;
    const float* yb = y + (size_t)b * NTOK * HID;
    #pragma unroll
    for (int rep = 0; rep < HID / 256; rep++) {
        int ch = threadIdx.x + rep * 256;
        float acc = bias[ch];
        #pragma unroll
        for (int dh = -1; dh <= 1; dh++) {
            int hh2 = h + dh;
            if (hh2 < 0 || hh2 >= HH) continue;
            #pragma unroll
            for (int dw = -1; dw <= 1; dw++) {
                int wc2 = wc + dw;
                if (wc2 < 0 || wc2 >= WW) continue;
                acc += yb[(size_t)(hh2 * WW + wc2) * HID + ch] * w[ch * 9 + (dh + 1) * 3 + (dw + 1)];
            }
        }
        float gv = 0.5f * acc * (1.f + erff(acc * 0.70710678118654752f));
        out[((size_t)b * NTOK + n) * HID + ch] = gv;
    }
}

// ---------------- launch ----------------
extern "C" void kernel_launch(void* const* d_in, const int* in_sizes, int n_in,
                              void* d_out, int out_size) {
    const float* feat0   = (const float*)d_in[0];
    const float* feat1   = (const float*)d_in[1];
    const float* norm1_g = (const float*)d_in[2];
    const float* norm1_b = (const float*)d_in[3];
    const float* norm2_g = (const float*)d_in[4];
    const float* norm2_b = (const float*)d_in[5];
    const float* q_w     = (const float*)d_in[6];
    const float* q_b     = (const float*)d_in[7];
    const float* kv_w    = (const float*)d_in[8];
    const float* kv_b    = (const float*)d_in[9];
    const float* cor_w   = (const float*)d_in[10];
    const float* cor_b   = (const float*)d_in[11];
    const float* mot_w   = (const float*)d_in[12];
    const float* mot_b   = (const float*)d_in[13];
    const float* proj_w  = (const float*)d_in[14];
    const float* proj_b  = (const float*)d_in[15];
    const float* fc1_w   = (const float*)d_in[16];
    const float* fc1_b   = (const float*)d_in[17];
    const float* dw_w    = (const float*)d_in[18];
    const float* dw_b    = (const float*)d_in[19];
    const float* fc2_w   = (const float*)d_in[20];
    const float* fc2_b   = (const float*)d_in[21];

    float* out_main   = (float*)d_out;                          // (4,256,2304)
    float* out_motion = out_main + (size_t)BATCH * CDIM * NTOK; // (4,128,2304)

    float *pS, *pQ, *pKV, *pXO, *pCR, *pS2, *pN2, *pY1, *pY2, *pZ, *pMO;
    cudaGetSymbolAddress((void**)&pS,  g_S);
    cudaGetSymbolAddress((void**)&pQ,  g_Q);
    cudaGetSymbolAddress((void**)&pKV, g_KV);
    cudaGetSymbolAddress((void**)&pXO, g_XO);
    cudaGetSymbolAddress((void**)&pCR, g_CR);
    cudaGetSymbolAddress((void**)&pS2, g_S2);
    cudaGetSymbolAddress((void**)&pN2, g_N2);
    cudaGetSymbolAddress((void**)&pY1, g_Y1);
    cudaGetSymbolAddress((void**)&pY2, g_Y2);
    cudaGetSymbolAddress((void**)&pZ,  g_Z);
    cudaGetSymbolAddress((void**)&pMO, g_MO);

    dim3 tb(32, 8);

    transpose_kernel<<<dim3(NTOK / 32, CDIM / 32, 2), tb>>>(feat0, pS, CDIM, NTOK);
    transpose_kernel<<<dim3(NTOK / 32, CDIM / 32, 2), tb>>>(feat1, pS + 2 * (size_t)NTOK * CDIM, CDIM, NTOK);
    ln_rows_kernel<<<(BATCH * NTOK) / 8, 256>>>(pS, pS, norm1_g, norm1_b, BATCH * NTOK);

    int M = BATCH * NTOK;
    gemm_kernel<<<dim3(CDIM / 128, M / 128), 256>>>(pS, q_w, q_b, nullptr, pQ,
                                                    M, CDIM, CDIM, 0, 0, nullptr, nullptr);
    gemm_kernel<<<dim3(2 * CDIM / 128, M / 128), 256>>>(pS, kv_w, kv_b, nullptr, pKV,
                                                        M, CDIM, 2 * CDIM, 1, 0, nullptr, nullptr);
    // fused attention + motion aggregation (tf32 tensor cores)
    size_t fsmem = (2304 + 3584 + 128 * 76) * sizeof(float);   // 62464 B
    cudaFuncSetAttribute(flash_kernel, cudaFuncAttributeMaxDynamicSharedMemorySize, (int)fsmem);
    flash_kernel<<<dim3(NTOK / 128, NHEAD, BATCH), 256, fsmem>>>(pQ, pKV, cor_w, cor_b, pXO, pCR);
    gemm_kernel<<<dim3(CDIM / 128, M / 128), 256>>>(pXO, proj_w, proj_b, pS, pS2,
                                                    M, CDIM, CDIM, 0, 0, nullptr, nullptr);
    ln_rows_kernel<<<(BATCH * NTOK) / 8, 256>>>(pS2, pN2, norm2_g, norm2_b, BATCH * NTOK);
    gemm_kernel<<<dim3(HID / 128, M / 128), 256>>>(pN2, fc1_w, fc1_b, nullptr, pY1,
                                                   M, CDIM, HID, 0, 0, nullptr, nullptr);
    dwconv_gelu_kernel<<<dim3(NTOK, BATCH), 256>>>(pY1, dw_w, dw_b, pY2);
    gemm_kernel<<<dim3(CDIM / 128, M / 128), 256>>>(pY2, fc2_w, fc2_b, pS2, pZ,
                                                    M, HID, CDIM, 0, 0, nullptr, nullptr);
    gemm_kernel<<<dim3(MDIM / 128, M / 128), 256>>>(pCR, mot_w, mot_b, nullptr, pMO,
                                                    M, MDIM, MDIM, 0, 1, cor_w, cor_b);
    transpose_kernel<<<dim3(CDIM / 32, NTOK / 32, BATCH), tb>>>(pZ, out_main, NTOK, CDIM);
    transpose_kernel<<<dim3(MDIM / 32, NTOK / 32, BATCH), tb>>>(pMO, out_motion, NTOK, MDIM);
}

// round 5
// speedup vs baseline: 2.9228x; 1.3352x over previous
#include <cuda_runtime.h>
#include <math.h>

#define NTOK 2304
#define CDIM 256
#define BATCH 4
#define NHEAD 8
#define HD 32
#define MDIM 128
#define MHD 16
#define HID 1024
#define HH 48
#define WW 48
#define SCALE 0.17677669529663687f

// ---------------- scratch (static __device__, no allocs) ----------------
__device__ float g_S [BATCH*NTOK*CDIM];     // normed tokens (feat_s)
__device__ float g_Q [BATCH*NTOK*CDIM];
__device__ float g_KV[BATCH*NTOK*2*CDIM];
__device__ float g_XO[BATCH*NTOK*CDIM];     // attn @ v (head-merged)
__device__ float g_CR[BATCH*NTOK*MDIM];     // attn @ ceh
__device__ float g_S2[BATCH*NTOK*CDIM];     // after proj + residual
__device__ float g_N2[BATCH*NTOK*CDIM];     // norm2 output
__device__ float g_Y1[BATCH*NTOK*HID];      // fc1 out
__device__ float g_Y2[BATCH*NTOK*HID];      // after dwconv+gelu
__device__ float g_Z [BATCH*NTOK*CDIM];     // fc2 out + residual
__device__ float g_MO[BATCH*NTOK*MDIM];     // motion (token-major)

// ---------------- tf32 helpers ----------------
__device__ __forceinline__ unsigned f2tf32(float f) {
    unsigned r;
    asm("cvt.rna.tf32.f32 %0, %1;" : "=r"(r) : "f"(f));
    return r;
}
__device__ __forceinline__ float f2tf32f(float f) {
    return __uint_as_float(f2tf32(f));
}
__device__ __forceinline__ void mma_tf32(float* c,
    unsigned a0, unsigned a1, unsigned a2, unsigned a3,
    unsigned b0, unsigned b1) {
    asm("mma.sync.aligned.m16n8k8.row.col.f32.tf32.tf32.f32 "
        "{%0,%1,%2,%3}, {%4,%5,%6,%7}, {%8,%9}, {%0,%1,%2,%3};"
        : "+f"(c[0]), "+f"(c[1]), "+f"(c[2]), "+f"(c[3])
        : "r"(a0), "r"(a1), "r"(a2), "r"(a3), "r"(b0), "r"(b1));
}

// ---------------- tiled transpose: in (B,R,C) -> out (B,C,R) ----------------
__global__ void transpose_kernel(const float* __restrict__ in, float* __restrict__ out,
                                 int R, int C) {
    __shared__ float t[32][33];
    int b = blockIdx.z;
    int r0 = blockIdx.y * 32, c0 = blockIdx.x * 32;
    const float* ib = in + (size_t)b * R * C;
    float* ob = out + (size_t)b * R * C;
    #pragma unroll
    for (int i = threadIdx.y; i < 32; i += 8) {
        t[i][threadIdx.x] = ib[(size_t)(r0 + i) * C + c0 + threadIdx.x];
    }
    __syncthreads();
    #pragma unroll
    for (int i = threadIdx.y; i < 32; i += 8) {
        ob[(size_t)(c0 + i) * R + r0 + threadIdx.x] = t[threadIdx.x][i];
    }
}

// ---------------- LayerNorm over last dim (C=256), warp per row ----------------
__global__ void ln_rows_kernel(const float* __restrict__ in, float* __restrict__ out,
                               const float* __restrict__ g, const float* __restrict__ bb,
                               int rows) {
    int warp = (blockIdx.x * blockDim.x + threadIdx.x) >> 5;
    int lane = threadIdx.x & 31;
    if (warp >= rows) return;
    const float* row = in + (size_t)warp * CDIM;
    float* orow = out + (size_t)warp * CDIM;
    float v[8];
    float s = 0.f, s2 = 0.f;
    #pragma unroll
    for (int i = 0; i < 8; i++) {
        v[i] = row[lane + i * 32];
        s += v[i];
        s2 += v[i] * v[i];
    }
    #pragma unroll
    for (int o = 16; o; o >>= 1) {
        s  += __shfl_xor_sync(0xffffffffu, s,  o);
        s2 += __shfl_xor_sync(0xffffffffu, s2, o);
    }
    float mean = s * (1.f / CDIM);
    float var  = s2 * (1.f / CDIM) - mean * mean;
    float rstd = rsqrtf(var + 1e-5f);
    #pragma unroll
    for (int i = 0; i < 8; i++) {
        int c = lane + i * 32;
        orow[c] = (v[i] - mean) * rstd * g[c] + bb[c];
    }
}

// ---------------- tf32 tensor-core GEMM: 128x128 tile, 8 warps (2x4) ----------------
// C[M,N] = op(A)[M,K] @ B[K,N] + bias[N] (+ resid[M,N])
// swapHalf: logical row (b,n) reads physical row (b^2, n)  [feat_t]
// subCE:    A element = A[m][k] - ce(n,k) (motion input)
__global__ __launch_bounds__(256)
void gemm_kernel(const float* __restrict__ A, const float* __restrict__ B,
                 const float* __restrict__ bias, const float* __restrict__ resid,
                 float* __restrict__ C, int M, int K, int N,
                 int swapHalf, int subCE,
                 const float* __restrict__ corw, const float* __restrict__ corb) {
    __shared__ float As[16][132];   // [k][m] tf32 bits
    __shared__ float Bs[16][132];   // [k][n] tf32 bits
    int tid = threadIdx.x;
    int wid = tid >> 5, lane = tid & 31;
    int gid = lane >> 2, tig = lane & 3;
    int wm = wid & 1, wn = wid >> 1;        // warp tile: rows wm*64+.., cols wn*32+..
    int m0 = blockIdx.y * 128, n0 = blockIdx.x * 128;

    float acc[4][4][4] = {};                // [mf][nf][c0..c3]

    // A loader: 2 chunks; thread covers (arow, 4-float quad aq)
    int gmp_l[2]; float cx_l[2], cy_l[2]; int arow_l[2], aq_l[2];
    #pragma unroll
    for (int it = 0; it < 2; it++) {
        int idx = tid + it * 256;
        int arow = idx >> 2, aq = idx & 3;
        arow_l[it] = arow; aq_l[it] = aq;
        int gm = m0 + arow;
        int gmp = gm;
        if (swapHalf) { int b = gm / NTOK; int n = gm - b * NTOK; gmp = (b ^ 2) * NTOK + n; }
        gmp_l[it] = gmp;
        cx_l[it] = 0.f; cy_l[it] = 0.f;
        if (subCE) {
            int n = gm % NTOK;
            cx_l[it] = -1.f + 2.f * (float)(n % WW) * (1.f / 47.f);
            cy_l[it] = -1.f + 2.f * (float)(n / WW) * (1.f / 47.f);
        }
    }

    for (int k0 = 0; k0 < K; k0 += 16) {
        // A tile -> As[k][m] (transposed scalar stores, tf32-rounded)
        #pragma unroll
        for (int it = 0; it < 2; it++) {
            int arow = arow_l[it], aq = aq_l[it], gmp = gmp_l[it];
            if (subCE) {
                #pragma unroll
                for (int i = 0; i < 4; i++) {
                    int k = k0 + aq * 4 + i;
                    float ce = cx_l[it] * corw[k] + cy_l[it] * corw[128 + k] + corb[k];
                    As[aq * 4 + i][arow] = f2tf32f(A[(size_t)gmp * K + k] - ce);
                }
            } else {
                float4 a4 = *(const float4*)&A[(size_t)gmp * K + k0 + aq * 4];
                As[aq * 4 + 0][arow] = f2tf32f(a4.x);
                As[aq * 4 + 1][arow] = f2tf32f(a4.y);
                As[aq * 4 + 2][arow] = f2tf32f(a4.z);
                As[aq * 4 + 3][arow] = f2tf32f(a4.w);
            }
        }
        // B tile -> Bs[k][n] (direct float4 stores, tf32-rounded)
        #pragma unroll
        for (int it = 0; it < 2; it++) {
            int idx = tid + it * 256;
            int brow = idx >> 5, bc = idx & 31;
            float4 b4 = *(const float4*)&B[(size_t)(k0 + brow) * N + n0 + bc * 4];
            b4.x = f2tf32f(b4.x); b4.y = f2tf32f(b4.y);
            b4.z = f2tf32f(b4.z); b4.w = f2tf32f(b4.w);
            *(float4*)&Bs[brow][bc * 4] = b4;
        }
        __syncthreads();
        #pragma unroll
        for (int ks = 0; ks < 2; ks++) {
            int kb = ks * 8;
            unsigned af[4][4];
            #pragma unroll
            for (int mf = 0; mf < 4; mf++) {
                int mr = wm * 64 + mf * 16 + gid;
                af[mf][0] = __float_as_uint(As[kb + tig][mr]);
                af[mf][1] = __float_as_uint(As[kb + tig][mr + 8]);
                af[mf][2] = __float_as_uint(As[kb + tig + 4][mr]);
                af[mf][3] = __float_as_uint(As[kb + tig + 4][mr + 8]);
            }
            unsigned bf[4][2];
            #pragma unroll
            for (int nf = 0; nf < 4; nf++) {
                int nc = wn * 32 + nf * 8 + gid;
                bf[nf][0] = __float_as_uint(Bs[kb + tig][nc]);
                bf[nf][1] = __float_as_uint(Bs[kb + tig + 4][nc]);
            }
            #pragma unroll
            for (int mf = 0; mf < 4; mf++)
                #pragma unroll
                for (int nf = 0; nf < 4; nf++)
                    mma_tf32(acc[mf][nf], af[mf][0], af[mf][1], af[mf][2], af[mf][3],
                             bf[nf][0], bf[nf][1]);
        }
        __syncthreads();
    }
    // epilogue: thread owns rows {gid, gid+8}, cols {2tig, 2tig+1} per fragment
    #pragma unroll
    for (int nf = 0; nf < 4; nf++) {
        int col = n0 + wn * 32 + nf * 8 + 2 * tig;
        float2 bi = *(const float2*)&bias[col];
        #pragma unroll
        for (int mf = 0; mf < 4; mf++) {
            #pragma unroll
            for (int r = 0; r < 2; r++) {
                int m = m0 + wm * 64 + mf * 16 + gid + 8 * r;
                float2 v = make_float2(acc[mf][nf][r * 2]     + bi.x,
                                       acc[mf][nf][r * 2 + 1] + bi.y);
                if (resid) {
                    float2 rv = *(const float2*)&resid[(size_t)m * N + col];
                    v.x += rv.x; v.y += rv.y;
                }
                *(float2*)&C[(size_t)m * N + col] = v;
            }
        }
    }
}

// ---------------- fused flash attention + motion aggregation (tf32 mma) ----------
__global__ __launch_bounds__(256)
void flash_kernel(const float* __restrict__ qb, const float* __restrict__ kvb,
                  const float* __restrict__ corw, const float* __restrict__ corb,
                  float* __restrict__ xo, float* __restrict__ cro) {
    extern __shared__ float sm[];
    float (*Ks)[36] = (float(*)[36])(sm);                 // 64 keys x 32 dims (tf32 bits)
    float (*Wt)[56] = (float(*)[56])(sm + 2304);          // 64 keys x [V(32)|CE(16)] (tf32 bits)
    float (*Pi)[76] = (float(*)[76])(sm + 2304 + 3584);   // 128 rows x 64 probs (tf32 bits)

    int tid = threadIdx.x;
    int wid = tid >> 5, lane = tid & 31;
    int gid = lane >> 2, tig = lane & 3;
    int m0 = blockIdx.x * 128;
    int h  = blockIdx.y;
    int b  = blockIdx.z;

    const float* qbase = qb + ((size_t)b * NTOK) * CDIM + h * HD;
    const float* kbase = kvb + ((size_t)b * NTOK) * (2 * CDIM) + h * HD;
    const float* vbase = kbase + CDIM;
    const float* cwh = corw + h * MHD;
    const float* cbh = corb + h * MHD;

    unsigned qa[4][4];
    {
        size_t r0 = (size_t)(m0 + wid * 16 + gid) * CDIM;
        size_t r1 = r0 + 8 * CDIM;
        #pragma unroll
        for (int ks = 0; ks < 4; ks++) {
            qa[ks][0] = f2tf32(qbase[r0 + ks * 8 + tig]);
            qa[ks][1] = f2tf32(qbase[r1 + ks * 8 + tig]);
            qa[ks][2] = f2tf32(qbase[r0 + ks * 8 + tig + 4]);
            qa[ks][3] = f2tf32(qbase[r1 + ks * 8 + tig + 4]);
        }
    }

    float m_r[2] = {-1e30f, -1e30f};
    float l_r[2] = {0.f, 0.f};
    float O[6][4] = {};

    int lkey = tid >> 2;
    int ld0  = (tid & 3) * 8;
    int lc0  = (tid & 3) * 4;

    for (int kt = 0; kt < NTOK / 64; kt++) {
        int n0g = kt * 64;
        __syncthreads();
        {
            const float* kr = &kbase[(size_t)(n0g + lkey) * (2 * CDIM) + ld0];
            float4 v0 = *(const float4*)kr;
            float4 v1 = *(const float4*)(kr + 4);
            uint4 u0 = make_uint4(f2tf32(v0.x), f2tf32(v0.y), f2tf32(v0.z), f2tf32(v0.w));
            uint4 u1 = make_uint4(f2tf32(v1.x), f2tf32(v1.y), f2tf32(v1.z), f2tf32(v1.w));
            *(uint4*)&Ks[lkey][ld0]     = u0;
            *(uint4*)&Ks[lkey][ld0 + 4] = u1;
            const float* vr = &vbase[(size_t)(n0g + lkey) * (2 * CDIM) + ld0];
            float4 w0 = *(const float4*)vr;
            float4 w1 = *(const float4*)(vr + 4);
            uint4 x0 = make_uint4(f2tf32(w0.x), f2tf32(w0.y), f2tf32(w0.z), f2tf32(w0.w));
            uint4 x1 = make_uint4(f2tf32(w1.x), f2tf32(w1.y), f2tf32(w1.z), f2tf32(w1.w));
            *(uint4*)&Wt[lkey][ld0]     = x0;
            *(uint4*)&Wt[lkey][ld0 + 4] = x1;
            int kn = n0g + lkey;
            float xf = -1.f + 2.f * (float)(kn % WW) * (1.f / 47.f);
            float yf = -1.f + 2.f * (float)(kn / WW) * (1.f / 47.f);
            uint4 ce;
            ce.x = f2tf32(xf * cwh[lc0 + 0] + yf * cwh[128 + lc0 + 0] + cbh[lc0 + 0]);
            ce.y = f2tf32(xf * cwh[lc0 + 1] + yf * cwh[128 + lc0 + 1] + cbh[lc0 + 1]);
            ce.z = f2tf32(xf * cwh[lc0 + 2] + yf * cwh[128 + lc0 + 2] + cbh[lc0 + 2]);
            ce.w = f2tf32(xf * cwh[lc0 + 3] + yf * cwh[128 + lc0 + 3] + cbh[lc0 + 3]);
            *(uint4*)&Wt[lkey][32 + lc0] = ce;
        }
        __syncthreads();

        float c[8][4] = {};
        #pragma unroll
        for (int j = 0; j < 8; j++) {
            #pragma unroll
            for (int ks = 0; ks < 4; ks++) {
                unsigned b0 = __float_as_uint(Ks[j * 8 + gid][ks * 8 + tig]);
                unsigned b1 = __float_as_uint(Ks[j * 8 + gid][ks * 8 + tig + 4]);
                mma_tf32(c[j], qa[ks][0], qa[ks][1], qa[ks][2], qa[ks][3], b0, b1);
            }
        }

        #pragma unroll
        for (int r = 0; r < 2; r++) {
            float mx = -1e30f;
            #pragma unroll
            for (int j = 0; j < 8; j++)
                mx = fmaxf(mx, fmaxf(c[j][r * 2], c[j][r * 2 + 1]));
            mx = fmaxf(mx, __shfl_xor_sync(0xffffffffu, mx, 1));
            mx = fmaxf(mx, __shfl_xor_sync(0xffffffffu, mx, 2));
            mx *= SCALE;
            float nm = fmaxf(m_r[r], mx);
            float alpha = __expf(m_r[r] - nm);
            m_r[r] = nm;
            int prow = wid * 16 + gid + 8 * r;
            float sum = 0.f;
            #pragma unroll
            for (int j = 0; j < 8; j++) {
                float p0 = __expf(c[j][r * 2]     * SCALE - nm);
                float p1 = __expf(c[j][r * 2 + 1] * SCALE - nm);
                sum += p0 + p1;
                uint2 pp = make_uint2(f2tf32(p0), f2tf32(p1));
                *(uint2*)&Pi[prow][j * 8 + 2 * tig] = pp;
            }
            sum += __shfl_xor_sync(0xffffffffu, sum, 1);
            sum += __shfl_xor_sync(0xffffffffu, sum, 2);
            l_r[r] = l_r[r] * alpha + sum;
            #pragma unroll
            for (int j = 0; j < 6; j++) {
                O[j][r * 2]     *= alpha;
                O[j][r * 2 + 1] *= alpha;
            }
        }
        #pragma unroll
        for (int ks = 0; ks < 8; ks++) {
            int kk = ks * 8;
            unsigned a0 = __float_as_uint(Pi[wid * 16 + gid][kk + tig]);
            unsigned a1 = __float_as_uint(Pi[wid * 16 + gid + 8][kk + tig]);
            unsigned a2 = __float_as_uint(Pi[wid * 16 + gid][kk + tig + 4]);
            unsigned a3 = __float_as_uint(Pi[wid * 16 + gid + 8][kk + tig + 4]);
            #pragma unroll
            for (int j = 0; j < 6; j++) {
                unsigned b0 = __float_as_uint(Wt[kk + tig][j * 8 + gid]);
                unsigned b1 = __float_as_uint(Wt[kk + tig + 4][j * 8 + gid]);
                mma_tf32(O[j], a0, a1, a2, a3, b0, b1);
            }
        }
    }

    #pragma unroll
    for (int r = 0; r < 2; r++) {
        float inv = 1.f / l_r[r];
        size_t gm = (size_t)b * NTOK + m0 + wid * 16 + gid + 8 * r;
        #pragma unroll
        for (int j = 0; j < 4; j++) {
            float2 ov = make_float2(O[j][r * 2] * inv, O[j][r * 2 + 1] * inv);
            *(float2*)&xo[gm * CDIM + h * HD + j * 8 + 2 * tig] = ov;
        }
        #pragma unroll
        for (int j = 4; j < 6; j++) {
            float2 ov = make_float2(O[j][r * 2] * inv, O[j][r * 2 + 1] * inv);
            *(float2*)&cro[gm * MDIM + h * MHD + (j - 4) * 8 + 2 * tig] = ov;
        }
    }
}

// ---------------- depthwise 3x3 conv + bias + exact GELU ----------------
__global__ void dwconv_gelu_kernel(const float* __restrict__ y, const float* __restrict__ w,
                                   const float* __restrict__ bias, float* __restrict__ out) {
    int n = blockIdx.x;
    int b = blockIdx.y;
    int h = n / WW, wc = n % WW;
    const float* yb = y + (size_t)b * NTOK * HID;
    #pragma unroll
    for (int rep = 0; rep < HID / 256; rep++) {
        int ch = threadIdx.x + rep * 256;
        float acc = bias[ch];
        #pragma unroll
        for (int dh = -1; dh <= 1; dh++) {
            int hh2 = h + dh;
            if (hh2 < 0 || hh2 >= HH) continue;
            #pragma unroll
            for (int dw = -1; dw <= 1; dw++) {
                int wc2 = wc + dw;
                if (wc2 < 0 || wc2 >= WW) continue;
                acc += yb[(size_t)(hh2 * WW + wc2) * HID + ch] * w[ch * 9 + (dh + 1) * 3 + (dw + 1)];
            }
        }
        float gv = 0.5f * acc * (1.f + erff(acc * 0.70710678118654752f));
        out[((size_t)b * NTOK + n) * HID + ch] = gv;
    }
}

// ---------------- launch ----------------
extern "C" void kernel_launch(void* const* d_in, const int* in_sizes, int n_in,
                              void* d_out, int out_size) {
    const float* feat0   = (const float*)d_in[0];
    const float* feat1   = (const float*)d_in[1];
    const float* norm1_g = (const float*)d_in[2];
    const float* norm1_b = (const float*)d_in[3];
    const float* norm2_g = (const float*)d_in[4];
    const float* norm2_b = (const float*)d_in[5];
    const float* q_w     = (const float*)d_in[6];
    const float* q_b     = (const float*)d_in[7];
    const float* kv_w    = (const float*)d_in[8];
    const float* kv_b    = (const float*)d_in[9];
    const float* cor_w   = (const float*)d_in[10];
    const float* cor_b   = (const float*)d_in[11];
    const float* mot_w   = (const float*)d_in[12];
    const float* mot_b   = (const float*)d_in[13];
    const float* proj_w  = (const float*)d_in[14];
    const float* proj_b  = (const float*)d_in[15];
    const float* fc1_w   = (const float*)d_in[16];
    const float* fc1_b   = (const float*)d_in[17];
    const float* dw_w    = (const float*)d_in[18];
    const float* dw_b    = (const float*)d_in[19];
    const float* fc2_w   = (const float*)d_in[20];
    const float* fc2_b   = (const float*)d_in[21];

    float* out_main   = (float*)d_out;                          // (4,256,2304)
    float* out_motion = out_main + (size_t)BATCH * CDIM * NTOK; // (4,128,2304)

    float *pS, *pQ, *pKV, *pXO, *pCR, *pS2, *pN2, *pY1, *pY2, *pZ, *pMO;
    cudaGetSymbolAddress((void**)&pS,  g_S);
    cudaGetSymbolAddress((void**)&pQ,  g_Q);
    cudaGetSymbolAddress((void**)&pKV, g_KV);
    cudaGetSymbolAddress((void**)&pXO, g_XO);
    cudaGetSymbolAddress((void**)&pCR, g_CR);
    cudaGetSymbolAddress((void**)&pS2, g_S2);
    cudaGetSymbolAddress((void**)&pN2, g_N2);
    cudaGetSymbolAddress((void**)&pY1, g_Y1);
    cudaGetSymbolAddress((void**)&pY2, g_Y2);
    cudaGetSymbolAddress((void**)&pZ,  g_Z);
    cudaGetSymbolAddress((void**)&pMO, g_MO);

    dim3 tb(32, 8);

    transpose_kernel<<<dim3(NTOK / 32, CDIM / 32, 2), tb>>>(feat0, pS, CDIM, NTOK);
    transpose_kernel<<<dim3(NTOK / 32, CDIM / 32, 2), tb>>>(feat1, pS + 2 * (size_t)NTOK * CDIM, CDIM, NTOK);
    ln_rows_kernel<<<(BATCH * NTOK) / 8, 256>>>(pS, pS, norm1_g, norm1_b, BATCH * NTOK);

    int M = BATCH * NTOK;
    gemm_kernel<<<dim3(CDIM / 128, M / 128), 256>>>(pS, q_w, q_b, nullptr, pQ,
                                                    M, CDIM, CDIM, 0, 0, nullptr, nullptr);
    gemm_kernel<<<dim3(2 * CDIM / 128, M / 128), 256>>>(pS, kv_w, kv_b, nullptr, pKV,
                                                        M, CDIM, 2 * CDIM, 1, 0, nullptr, nullptr);
    size_t fsmem = (2304 + 3584 + 128 * 76) * sizeof(float);   // 62464 B
    cudaFuncSetAttribute(flash_kernel, cudaFuncAttributeMaxDynamicSharedMemorySize, (int)fsmem);
    flash_kernel<<<dim3(NTOK / 128, NHEAD, BATCH), 256, fsmem>>>(pQ, pKV, cor_w, cor_b, pXO, pCR);
    gemm_kernel<<<dim3(CDIM / 128, M / 128), 256>>>(pXO, proj_w, proj_b, pS, pS2,
                                                    M, CDIM, CDIM, 0, 0, nullptr, nullptr);
    ln_rows_kernel<<<(BATCH * NTOK) / 8, 256>>>(pS2, pN2, norm2_g, norm2_b, BATCH * NTOK);
    gemm_kernel<<<dim3(HID / 128, M / 128), 256>>>(pN2, fc1_w, fc1_b, nullptr, pY1,
                                                   M, CDIM, HID, 0, 0, nullptr, nullptr);
    dwconv_gelu_kernel<<<dim3(NTOK, BATCH), 256>>>(pY1, dw_w, dw_b, pY2);
    gemm_kernel<<<dim3(CDIM / 128, M / 128), 256>>>(pY2, fc2_w, fc2_b, pS2, pZ,
                                                    M, HID, CDIM, 0, 0, nullptr, nullptr);
    gemm_kernel<<<dim3(MDIM / 128, M / 128), 256>>>(pCR, mot_w, mot_b, nullptr, pMO,
                                                    M, MDIM, MDIM, 0, 1, cor_w, cor_b);
    transpose_kernel<<<dim3(CDIM / 32, NTOK / 32, BATCH), tb>>>(pZ, out_main, NTOK, CDIM);
    transpose_kernel<<<dim3(MDIM / 32, NTOK / 32, BATCH), tb>>>(pMO, out_motion, NTOK, MDIM);
}

// round 7
// speedup vs baseline: 3.2347x; 1.1067x over previous
#include <cuda_runtime.h>
#include <math.h>

#define NTOK 2304
#define CDIM 256
#define BATCH 4
#define NHEAD 8
#define HD 32
#define MDIM 128
#define MHD 16
#define HID 1024
#define HH 48
#define WW 48
#define SCALE 0.17677669529663687f

// ---------------- scratch (static __device__, no allocs) ----------------
__device__ float g_S [BATCH*NTOK*CDIM];
__device__ float g_Q [BATCH*NTOK*CDIM];
__device__ float g_KV[BATCH*NTOK*2*CDIM];
__device__ float g_XO[BATCH*NTOK*CDIM];
__device__ float g_CR[BATCH*NTOK*MDIM];
__device__ float g_S2[BATCH*NTOK*CDIM];
__device__ float g_N2[BATCH*NTOK*CDIM];
__device__ float g_Y1[BATCH*NTOK*HID];
__device__ float g_Y2[BATCH*NTOK*HID];
__device__ float g_Z [BATCH*NTOK*CDIM];
__device__ float g_MO[BATCH*NTOK*MDIM];

// ---------------- tf32 helpers ----------------
__device__ __forceinline__ unsigned f2tf32(float f) {
    unsigned r;
    asm("cvt.rna.tf32.f32 %0, %1;" : "=r"(r) : "f"(f));
    return r;
}
__device__ __forceinline__ float f2tf32f(float f) {
    return __uint_as_float(f2tf32(f));
}
__device__ __forceinline__ void mma_tf32(float* c,
    unsigned a0, unsigned a1, unsigned a2, unsigned a3,
    unsigned b0, unsigned b1) {
    asm("mma.sync.aligned.m16n8k8.row.col.f32.tf32.tf32.f32 "
        "{%0,%1,%2,%3}, {%4,%5,%6,%7}, {%8,%9}, {%0,%1,%2,%3};"
        : "+f"(c[0]), "+f"(c[1]), "+f"(c[2]), "+f"(c[3])
        : "r"(a0), "r"(a1), "r"(a2), "r"(a3), "r"(b0), "r"(b1));
}

// ---------------- tiled transpose: in (B,R,C) -> out (B,C,R) ----------------
__global__ void transpose_kernel(const float* __restrict__ in, float* __restrict__ out,
                                 int R, int C) {
    __shared__ float t[32][33];
    int b = blockIdx.z;
    int r0 = blockIdx.y * 32, c0 = blockIdx.x * 32;
    const float* ib = in + (size_t)b * R * C;
    float* ob = out + (size_t)b * R * C;
    #pragma unroll
    for (int i = threadIdx.y; i < 32; i += 8) {
        t[i][threadIdx.x] = ib[(size_t)(r0 + i) * C + c0 + threadIdx.x];
    }
    __syncthreads();
    #pragma unroll
    for (int i = threadIdx.y; i < 32; i += 8) {
        ob[(size_t)(c0 + i) * R + r0 + threadIdx.x] = t[threadIdx.x][i];
    }
}

// ---------------- LayerNorm over last dim (C=256), warp per row ----------------
__global__ void ln_rows_kernel(const float* __restrict__ in, float* __restrict__ out,
                               const float* __restrict__ g, const float* __restrict__ bb,
                               int rows) {
    int warp = (blockIdx.x * blockDim.x + threadIdx.x) >> 5;
    int lane = threadIdx.x & 31;
    if (warp >= rows) return;
    const float* row = in + (size_t)warp * CDIM;
    float* orow = out + (size_t)warp * CDIM;
    float v[8];
    float s = 0.f, s2 = 0.f;
    #pragma unroll
    for (int i = 0; i < 8; i++) {
        v[i] = row[lane + i * 32];
        s += v[i];
        s2 += v[i] * v[i];
    }
    #pragma unroll
    for (int o = 16; o; o >>= 1) {
        s  += __shfl_xor_sync(0xffffffffu, s,  o);
        s2 += __shfl_xor_sync(0xffffffffu, s2, o);
    }
    float mean = s * (1.f / CDIM);
    float var  = s2 * (1.f / CDIM) - mean * mean;
    float rstd = rsqrtf(var + 1e-5f);
    #pragma unroll
    for (int i = 0; i < 8; i++) {
        int c = lane + i * 32;
        orow[c] = (v[i] - mean) * rstd * g[c] + bb[c];
    }
}

// ---------------- tf32 tensor-core GEMM, double-buffered pipeline ----------------
// C[M,N] = op(A)[M,K] @ B[K,N] + bias[N] (+ resid[M,N])
__global__ __launch_bounds__(256)
void gemm_kernel(const float* __restrict__ A, const float* __restrict__ B,
                 const float* __restrict__ bias, const float* __restrict__ resid,
                 float* __restrict__ C, int M, int K, int N,
                 int swapHalf, int subCE,
                 const float* __restrict__ corw, const float* __restrict__ corb) {
    __shared__ float As[2][16][132];   // [stage][k][m] tf32 bits
    __shared__ float Bs[2][16][132];   // [stage][k][n] tf32 bits
    int tid = threadIdx.x;
    int wid = tid >> 5, lane = tid & 31;
    int gid = lane >> 2, tig = lane & 3;
    int wm = wid & 1, wn = wid >> 1;
    int m0 = blockIdx.y * 128, n0 = blockIdx.x * 128;

    float acc[4][4][4] = {};

    // loader geometry
    int gmp_l[2]; float cx_l[2], cy_l[2]; int arow_l[2], aq_l[2];
    int brow_l[2], bc_l[2];
    #pragma unroll
    for (int it = 0; it < 2; it++) {
        int idx = tid + it * 256;
        int arow = idx >> 2, aq = idx & 3;
        arow_l[it] = arow; aq_l[it] = aq;
        int gm = m0 + arow;
        int gmp = gm;
        if (swapHalf) { int b = gm / NTOK; int n = gm - b * NTOK; gmp = (b ^ 2) * NTOK + n; }
        gmp_l[it] = gmp;
        cx_l[it] = 0.f; cy_l[it] = 0.f;
        if (subCE) {
            int n = gm % NTOK;
            cx_l[it] = -1.f + 2.f * (float)(n % WW) * (1.f / 47.f);
            cy_l[it] = -1.f + 2.f * (float)(n / WW) * (1.f / 47.f);
        }
        brow_l[it] = idx >> 5; bc_l[it] = idx & 31;
    }

    float aR[2][4]; float4 bR[2];
    int nIter = K >> 4;

    // FETCH: issue LDGs for k0 into registers
    #define FETCH(k0) {                                                         \
        _Pragma("unroll")                                                       \
        for (int it = 0; it < 2; it++) {                                        \
            if (subCE) {                                                        \
                _Pragma("unroll")                                               \
                for (int i = 0; i < 4; i++) {                                   \
                    int k = (k0) + aq_l[it] * 4 + i;                            \
                    float ce = cx_l[it] * corw[k] + cy_l[it] * corw[128 + k] + corb[k]; \
                    aR[it][i] = A[(size_t)gmp_l[it] * K + k] - ce;              \
                }                                                               \
            } else {                                                            \
                *(float4*)&aR[it][0] =                                          \
                    *(const float4*)&A[(size_t)gmp_l[it] * K + (k0) + aq_l[it] * 4]; \
            }                                                                   \
            bR[it] = *(const float4*)&B[(size_t)((k0) + brow_l[it]) * N + n0 + bc_l[it] * 4]; \
        }                                                                       \
    }
    // STORE: regs -> smem stage s (tf32-rounded)
    #define STORE(s) {                                                          \
        _Pragma("unroll")                                                       \
        for (int it = 0; it < 2; it++) {                                        \
            As[s][aq_l[it] * 4 + 0][arow_l[it]] = f2tf32f(aR[it][0]);           \
            As[s][aq_l[it] * 4 + 1][arow_l[it]] = f2tf32f(aR[it][1]);           \
            As[s][aq_l[it] * 4 + 2][arow_l[it]] = f2tf32f(aR[it][2]);           \
            As[s][aq_l[it] * 4 + 3][arow_l[it]] = f2tf32f(aR[it][3]);           \
            float4 b4 = bR[it];                                                 \
            b4.x = f2tf32f(b4.x); b4.y = f2tf32f(b4.y);                         \
            b4.z = f2tf32f(b4.z); b4.w = f2tf32f(b4.w);                         \
            *(float4*)&Bs[s][brow_l[it]][bc_l[it] * 4] = b4;                    \
        }                                                                       \
    }

    FETCH(0);
    STORE(0);

    for (int ki = 0; ki < nIter; ki++) {
        __syncthreads();
        if (ki + 1 < nIter) FETCH((ki + 1) << 4);
        int s = ki & 1;
        #pragma unroll
        for (int ks = 0; ks < 2; ks++) {
            int kb = ks * 8;
            unsigned af[4][4];
            #pragma unroll
            for (int mf = 0; mf < 4; mf++) {
                int mr = wm * 64 + mf * 16 + gid;
                af[mf][0] = __float_as_uint(As[s][kb + tig][mr]);
                af[mf][1] = __float_as_uint(As[s][kb + tig][mr + 8]);
                af[mf][2] = __float_as_uint(As[s][kb + tig + 4][mr]);
                af[mf][3] = __float_as_uint(As[s][kb + tig + 4][mr + 8]);
            }
            unsigned bf[4][2];
            #pragma unroll
            for (int nf = 0; nf < 4; nf++) {
                int nc = wn * 32 + nf * 8 + gid;
                bf[nf][0] = __float_as_uint(Bs[s][kb + tig][nc]);
                bf[nf][1] = __float_as_uint(Bs[s][kb + tig + 4][nc]);
            }
            #pragma unroll
            for (int mf = 0; mf < 4; mf++)
                #pragma unroll
                for (int nf = 0; nf < 4; nf++)
                    mma_tf32(acc[mf][nf], af[mf][0], af[mf][1], af[mf][2], af[mf][3],
                             bf[nf][0], bf[nf][1]);
        }
        if (ki + 1 < nIter) STORE((ki + 1) & 1);
    }
    #undef FETCH
    #undef STORE

    // epilogue
    #pragma unroll
    for (int nf = 0; nf < 4; nf++) {
        int col = n0 + wn * 32 + nf * 8 + 2 * tig;
        float2 bi = *(const float2*)&bias[col];
        #pragma unroll
        for (int mf = 0; mf < 4; mf++) {
            #pragma unroll
            for (int r = 0; r < 2; r++) {
                int m = m0 + wm * 64 + mf * 16 + gid + 8 * r;
                float2 v = make_float2(acc[mf][nf][r * 2]     + bi.x,
                                       acc[mf][nf][r * 2 + 1] + bi.y);
                if (resid) {
                    float2 rv = *(const float2*)&resid[(size_t)m * N + col];
                    v.x += rv.x; v.y += rv.y;
                }
                *(float2*)&C[(size_t)m * N + col] = v;
            }
        }
    }
}

// ---------------- fused flash attention + motion aggregation (tf32 mma) ----------
// Register prefetch of next K/V tile hides LDG latency behind MMA/softmax/PV.
__global__ __launch_bounds__(256)
void flash_kernel(const float* __restrict__ qb, const float* __restrict__ kvb,
                  const float* __restrict__ corw, const float* __restrict__ corb,
                  float* __restrict__ xo, float* __restrict__ cro) {
    extern __shared__ float sm[];
    float (*Ks)[36] = (float(*)[36])(sm);                 // 64 keys x 32 dims
    float (*Wt)[56] = (float(*)[56])(sm + 2304);          // 64 keys x [V|CE]
    float (*Pi)[76] = (float(*)[76])(sm + 2304 + 3584);   // 128 rows x 64 probs

    int tid = threadIdx.x;
    int wid = tid >> 5, lane = tid & 31;
    int gid = lane >> 2, tig = lane & 3;
    int m0 = blockIdx.x * 128;
    int h  = blockIdx.y;
    int b  = blockIdx.z;

    const float* qbase = qb + ((size_t)b * NTOK) * CDIM + h * HD;
    const float* kbase = kvb + ((size_t)b * NTOK) * (2 * CDIM) + h * HD;
    const float* vbase = kbase + CDIM;
    const float* cwh = corw + h * MHD;
    const float* cbh = corb + h * MHD;

    unsigned qa[4][4];
    {
        size_t r0 = (size_t)(m0 + wid * 16 + gid) * CDIM;
        size_t r1 = r0 + 8 * CDIM;
        #pragma unroll
        for (int ks = 0; ks < 4; ks++) {
            qa[ks][0] = f2tf32(qbase[r0 + ks * 8 + tig]);
            qa[ks][1] = f2tf32(qbase[r1 + ks * 8 + tig]);
            qa[ks][2] = f2tf32(qbase[r0 + ks * 8 + tig + 4]);
            qa[ks][3] = f2tf32(qbase[r1 + ks * 8 + tig + 4]);
        }
    }

    float m_r[2] = {-1e30f, -1e30f};
    float l_r[2] = {0.f, 0.f};
    float O[6][4] = {};

    int lkey = tid >> 2;
    int ld0  = (tid & 3) * 8;
    int lc0  = (tid & 3) * 4;

    // prefetch tile 0 K/V rows into registers
    float4 kR0, kR1, vR0, vR1;
    {
        const float* kr = &kbase[(size_t)lkey * (2 * CDIM) + ld0];
        kR0 = *(const float4*)kr; kR1 = *(const float4*)(kr + 4);
        const float* vr = &vbase[(size_t)lkey * (2 * CDIM) + ld0];
        vR0 = *(const float4*)vr; vR1 = *(const float4*)(vr + 4);
    }

    const int NT = NTOK / 64;
    for (int kt = 0; kt < NT; kt++) {
        int n0g = kt * 64;
        __syncthreads();   // prior-iter readers of Ks/Wt done
        // store prefetched K/V (tf32) + CE compute
        {
            uint4 u0 = make_uint4(f2tf32(kR0.x), f2tf32(kR0.y), f2tf32(kR0.z), f2tf32(kR0.w));
            uint4 u1 = make_uint4(f2tf32(kR1.x), f2tf32(kR1.y), f2tf32(kR1.z), f2tf32(kR1.w));
            *(uint4*)&Ks[lkey][ld0]     = u0;
            *(uint4*)&Ks[lkey][ld0 + 4] = u1;
            uint4 x0 = make_uint4(f2tf32(vR0.x), f2tf32(vR0.y), f2tf32(vR0.z), f2tf32(vR0.w));
            uint4 x1 = make_uint4(f2tf32(vR1.x), f2tf32(vR1.y), f2tf32(vR1.z), f2tf32(vR1.w));
            *(uint4*)&Wt[lkey][ld0]     = x0;
            *(uint4*)&Wt[lkey][ld0 + 4] = x1;
            int kn = n0g + lkey;
            float xf = -1.f + 2.f * (float)(kn % WW) * (1.f / 47.f);
            float yf = -1.f + 2.f * (float)(kn / WW) * (1.f / 47.f);
            uint4 ce;
            ce.x = f2tf32(xf * cwh[lc0 + 0] + yf * cwh[128 + lc0 + 0] + cbh[lc0 + 0]);
            ce.y = f2tf32(xf * cwh[lc0 + 1] + yf * cwh[128 + lc0 + 1] + cbh[lc0 + 1]);
            ce.z = f2tf32(xf * cwh[lc0 + 2] + yf * cwh[128 + lc0 + 2] + cbh[lc0 + 2]);
            ce.w = f2tf32(xf * cwh[lc0 + 3] + yf * cwh[128 + lc0 + 3] + cbh[lc0 + 3]);
            *(uint4*)&Wt[lkey][32 + lc0] = ce;
        }
        __syncthreads();
        // prefetch next tile (LDG latency hidden behind QK/softmax/PV)
        if (kt + 1 < NT) {
            const float* kr = &kbase[(size_t)(n0g + 64 + lkey) * (2 * CDIM) + ld0];
            kR0 = *(const float4*)kr; kR1 = *(const float4*)(kr + 4);
            const float* vr = &vbase[(size_t)(n0g + 64 + lkey) * (2 * CDIM) + ld0];
            vR0 = *(const float4*)vr; vR1 = *(const float4*)(vr + 4);
        }

        float c[8][4] = {};
        #pragma unroll
        for (int j = 0; j < 8; j++) {
            #pragma unroll
            for (int ks = 0; ks < 4; ks++) {
                unsigned b0 = __float_as_uint(Ks[j * 8 + gid][ks * 8 + tig]);
                unsigned b1 = __float_as_uint(Ks[j * 8 + gid][ks * 8 + tig + 4]);
                mma_tf32(c[j], qa[ks][0], qa[ks][1], qa[ks][2], qa[ks][3], b0, b1);
            }
        }

        #pragma unroll
        for (int r = 0; r < 2; r++) {
            float mx = -1e30f;
            #pragma unroll
            for (int j = 0; j < 8; j++)
                mx = fmaxf(mx, fmaxf(c[j][r * 2], c[j][r * 2 + 1]));
            mx = fmaxf(mx, __shfl_xor_sync(0xffffffffu, mx, 1));
            mx = fmaxf(mx, __shfl_xor_sync(0xffffffffu, mx, 2));
            mx *= SCALE;
            float nm = fmaxf(m_r[r], mx);
            float alpha = __expf(m_r[r] - nm);
            m_r[r] = nm;
            int prow = wid * 16 + gid + 8 * r;
            float sum = 0.f;
            #pragma unroll
            for (int j = 0; j < 8; j++) {
                float p0 = __expf(c[j][r * 2]     * SCALE - nm);
                float p1 = __expf(c[j][r * 2 + 1] * SCALE - nm);
                sum += p0 + p1;
                uint2 pp = make_uint2(f2tf32(p0), f2tf32(p1));
                *(uint2*)&Pi[prow][j * 8 + 2 * tig] = pp;
            }
            sum += __shfl_xor_sync(0xffffffffu, sum, 1);
            sum += __shfl_xor_sync(0xffffffffu, sum, 2);
            l_r[r] = l_r[r] * alpha + sum;
            #pragma unroll
            for (int j = 0; j < 6; j++) {
                O[j][r * 2]     *= alpha;
                O[j][r * 2 + 1] *= alpha;
            }
        }
        #pragma unroll
        for (int ks = 0; ks < 8; ks++) {
            int kk = ks * 8;
            unsigned a0 = __float_as_uint(Pi[wid * 16 + gid][kk + tig]);
            unsigned a1 = __float_as_uint(Pi[wid * 16 + gid + 8][kk + tig]);
            unsigned a2 = __float_as_uint(Pi[wid * 16 + gid][kk + tig + 4]);
            unsigned a3 = __float_as_uint(Pi[wid * 16 + gid + 8][kk + tig + 4]);
            #pragma unroll
            for (int j = 0; j < 6; j++) {
                unsigned b0 = __float_as_uint(Wt[kk + tig][j * 8 + gid]);
                unsigned b1 = __float_as_uint(Wt[kk + tig + 4][j * 8 + gid]);
                mma_tf32(O[j], a0, a1, a2, a3, b0, b1);
            }
        }
    }

    #pragma unroll
    for (int r = 0; r < 2; r++) {
        float inv = 1.f / l_r[r];
        size_t gm = (size_t)b * NTOK + m0 + wid * 16 + gid + 8 * r;
        #pragma unroll
        for (int j = 0; j < 4; j++) {
            float2 ov = make_float2(O[j][r * 2] * inv, O[j][r * 2 + 1] * inv);
            *(float2*)&xo[gm * CDIM + h * HD + j * 8 + 2 * tig] = ov;
        }
        #pragma unroll
        for (int j = 4; j < 6; j++) {
            float2 ov = make_float2(O[j][r * 2] * inv, O[j][r * 2 + 1] * inv);
            *(float2*)&cro[gm * MDIM + h * MHD + (j - 4) * 8 + 2 * tig] = ov;
        }
    }
}

// ---------------- depthwise 3x3 conv + bias + exact GELU ----------------
__global__ void dwconv_gelu_kernel(const float* __restrict__ y, const float* __restrict__ w,
                                   const float* __restrict__ bias, float* __restrict__ out) {
    int n = blockIdx.x;
    int b = blockIdx.y;
    int h = n / WW, wc = n % WW;
    const float* yb = y + (size_t)b * NTOK * HID;
    #pragma unroll
    for (int rep = 0; rep < HID / 256; rep++) {
        int ch = threadIdx.x + rep * 256;
        float acc = bias[ch];
        #pragma unroll
        for (int dh = -1; dh <= 1; dh++) {
            int hh2 = h + dh;
            if (hh2 < 0 || hh2 >= HH) continue;
            #pragma unroll
            for (int dw = -1; dw <= 1; dw++) {
                int wc2 = wc + dw;
                if (wc2 < 0 || wc2 >= WW) continue;
                acc += yb[(size_t)(hh2 * WW + wc2) * HID + ch] * w[ch * 9 + (dh + 1) * 3 + (dw + 1)];
            }
        }
        float gv = 0.5f * acc * (1.f + erff(acc * 0.70710678118654752f));
        out[((size_t)b * NTOK + n) * HID + ch] = gv;
    }
}

// ---------------- launch ----------------
extern "C" void kernel_launch(void* const* d_in, const int* in_sizes, int n_in,
                              void* d_out, int out_size) {
    const float* feat0   = (const float*)d_in[0];
    const float* feat1   = (const float*)d_in[1];
    const float* norm1_g = (const float*)d_in[2];
    const float* norm1_b = (const float*)d_in[3];
    const float* norm2_g = (const float*)d_in[4];
    const float* norm2_b = (const float*)d_in[5];
    const float* q_w     = (const float*)d_in[6];
    const float* q_b     = (const float*)d_in[7];
    const float* kv_w    = (const float*)d_in[8];
    const float* kv_b    = (const float*)d_in[9];
    const float* cor_w   = (const float*)d_in[10];
    const float* cor_b   = (const float*)d_in[11];
    const float* mot_w   = (const float*)d_in[12];
    const float* mot_b   = (const float*)d_in[13];
    const float* proj_w  = (const float*)d_in[14];
    const float* proj_b  = (const float*)d_in[15];
    const float* fc1_w   = (const float*)d_in[16];
    const float* fc1_b   = (const float*)d_in[17];
    const float* dw_w    = (const float*)d_in[18];
    const float* dw_b    = (const float*)d_in[19];
    const float* fc2_w   = (const float*)d_in[20];
    const float* fc2_b   = (const float*)d_in[21];

    float* out_main   = (float*)d_out;
    float* out_motion = out_main + (size_t)BATCH * CDIM * NTOK;

    float *pS, *pQ, *pKV, *pXO, *pCR, *pS2, *pN2, *pY1, *pY2, *pZ, *pMO;
    cudaGetSymbolAddress((void**)&pS,  g_S);
    cudaGetSymbolAddress((void**)&pQ,  g_Q);
    cudaGetSymbolAddress((void**)&pKV, g_KV);
    cudaGetSymbolAddress((void**)&pXO, g_XO);
    cudaGetSymbolAddress((void**)&pCR, g_CR);
    cudaGetSymbolAddress((void**)&pS2, g_S2);
    cudaGetSymbolAddress((void**)&pN2, g_N2);
    cudaGetSymbolAddress((void**)&pY1, g_Y1);
    cudaGetSymbolAddress((void**)&pY2, g_Y2);
    cudaGetSymbolAddress((void**)&pZ,  g_Z);
    cudaGetSymbolAddress((void**)&pMO, g_MO);

    dim3 tb(32, 8);

    transpose_kernel<<<dim3(NTOK / 32, CDIM / 32, 2), tb>>>(feat0, pS, CDIM, NTOK);
    transpose_kernel<<<dim3(NTOK / 32, CDIM / 32, 2), tb>>>(feat1, pS + 2 * (size_t)NTOK * CDIM, CDIM, NTOK);
    ln_rows_kernel<<<(BATCH * NTOK) / 8, 256>>>(pS, pS, norm1_g, norm1_b, BATCH * NTOK);

    int M = BATCH * NTOK;
    gemm_kernel<<<dim3(CDIM / 128, M / 128), 256>>>(pS, q_w, q_b, nullptr, pQ,
                                                    M, CDIM, CDIM, 0, 0, nullptr, nullptr);
    gemm_kernel<<<dim3(2 * CDIM / 128, M / 128), 256>>>(pS, kv_w, kv_b, nullptr, pKV,
                                                        M, CDIM, 2 * CDIM, 1, 0, nullptr, nullptr);
    size_t fsmem = (2304 + 3584 + 128 * 76) * sizeof(float);   // 62464 B
    cudaFuncSetAttribute(flash_kernel, cudaFuncAttributeMaxDynamicSharedMemorySize, (int)fsmem);
    flash_kernel<<<dim3(NTOK / 128, NHEAD, BATCH), 256, fsmem>>>(pQ, pKV, cor_w, cor_b, pXO, pCR);
    gemm_kernel<<<dim3(CDIM / 128, M / 128), 256>>>(pXO, proj_w, proj_b, pS, pS2,
                                                    M, CDIM, CDIM, 0, 0, nullptr, nullptr);
    ln_rows_kernel<<<(BATCH * NTOK) / 8, 256>>>(pS2, pN2, norm2_g, norm2_b, BATCH * NTOK);
    gemm_kernel<<<dim3(HID / 128, M / 128), 256>>>(pN2, fc1_w, fc1_b, nullptr, pY1,
                                                   M, CDIM, HID, 0, 0, nullptr, nullptr);
    dwconv_gelu_kernel<<<dim3(NTOK, BATCH), 256>>>(pY1, dw_w, dw_b, pY2);
    gemm_kernel<<<dim3(CDIM / 128, M / 128), 256>>>(pY2, fc2_w, fc2_b, pS2, pZ,
                                                    M, HID, CDIM, 0, 0, nullptr, nullptr);
    gemm_kernel<<<dim3(MDIM / 128, M / 128), 256>>>(pCR, mot_w, mot_b, nullptr, pMO,
                                                    M, MDIM, MDIM, 0, 1, cor_w, cor_b);
    transpose_kernel<<<dim3(CDIM / 32, NTOK / 32, BATCH), tb>>>(pZ, out_main, NTOK, CDIM);
    transpose_kernel<<<dim3(MDIM / 32, NTOK / 32, BATCH), tb>>>(pMO, out_motion, NTOK, MDIM);
}